// round 6
// baseline (speedup 1.0000x reference)
#include <cuda_runtime.h>
#include <cstdint>

// Problem constants
#define Bq 64
#define Sq 512
#define Eq 1024
#define Hq 1024
#define Gq 4096     // 4*H
#define Oq 50
#define KOUT 2048   // 2*H

// ---------------- scratch (device globals; no runtime allocation) ----------
__device__ float g_x  [(size_t)Sq*Bq*Eq];   // embedded input, (S,B,E)
__device__ float g_hf1[(size_t)Sq*Bq*Hq];   // fwd layer-1 output (S,B,H)
__device__ float g_hb1[(size_t)Sq*Bq*Hq];   // bwd layer-1 output (u=reversed time)
__device__ float g_hf2[(size_t)Sq*Bq*Hq];   // fwd layer-2 output
__device__ float g_hb2[(size_t)Sq*Bq*Hq];   // bwd layer-2 output (u order)
__device__ float g_gf [(size_t)Sq*Bq*Gq];   // fwd pre-gates for current layer
__device__ float g_gb [(size_t)Sq*Bq*Gq];   // bwd pre-gates for current layer
__device__ float g_c  [2*Bq*Hq];            // cell state per direction

// grid-barrier state (monotonic across launches & graph replays)
__device__ volatile unsigned g_flags[128];
__device__ unsigned g_epoch = 0;

// ---------------- helpers ---------------------------------------------------
__device__ __forceinline__ float sigf(float x) {
    return __fdividef(1.0f, 1.0f + __expf(-x));
}
__device__ __forceinline__ float tanhfast(float x) {
    return __fdividef(2.0f, 1.0f + __expf(-2.0f * x)) - 1.0f;
}

// ---------------- embedding gather ------------------------------------------
__global__ void embed_k(const int* __restrict__ src, const float* __restrict__ emb) {
    int row = blockIdx.x;           // s*B + b
    int s = row >> 6;
    int b = row & 63;
    int v = src[b * Sq + s];
    const float4* e4 = reinterpret_cast<const float4*>(emb + (size_t)v * Eq);
    float4* d4 = reinterpret_cast<float4*>(g_x + (size_t)row * Eq);
    d4[threadIdx.x] = e4[threadIdx.x];
}

// ---------------- pre-gates GEMM: gates = in @ Wih^T + bias ------------------
__global__ __launch_bounds__(256) void pregemm_k(
    int insel, const float* __restrict__ W0, const float* __restrict__ bias,
    int dirout, int rev)
{
    __shared__ float As[16][64];
    __shared__ float Ws[16][64];
    const float* in = (insel == 0) ? g_x : ((insel == 1) ? g_hf1 : g_hb1);
    float* gates = dirout ? g_gb : g_gf;

    int t   = blockIdx.y;
    int tin = rev ? (Sq - 1 - t) : t;
    int nb  = blockIdx.x;
    const float* A = in + (size_t)tin * Bq * Eq;
    const float* W = W0 + (size_t)nb * 64 * Eq;

    int tid = threadIdx.x;
    int lm = tid >> 4, lk = tid & 15;
    int ty = lm, tx = lk;

    float acc[4][4];
#pragma unroll
    for (int i = 0; i < 4; i++)
#pragma unroll
        for (int j = 0; j < 4; j++) acc[i][j] = 0.0f;

    for (int k0 = 0; k0 < Eq; k0 += 16) {
#pragma unroll
        for (int i = 0; i < 4; i++) {
            As[lk][lm + i * 16] = A[(size_t)(lm + i * 16) * Eq + k0 + lk];
            Ws[lk][lm + i * 16] = W[(size_t)(lm + i * 16) * Eq + k0 + lk];
        }
        __syncthreads();
#pragma unroll
        for (int kk = 0; kk < 16; kk++) {
            float4 av = *reinterpret_cast<const float4*>(&As[kk][ty * 4]);
            float4 wv = *reinterpret_cast<const float4*>(&Ws[kk][tx * 4]);
            float a[4] = {av.x, av.y, av.z, av.w};
            float w[4] = {wv.x, wv.y, wv.z, wv.w};
#pragma unroll
            for (int i = 0; i < 4; i++)
#pragma unroll
                for (int j = 0; j < 4; j++) acc[i][j] += a[i] * w[j];
        }
        __syncthreads();
    }

    float4 bv = *reinterpret_cast<const float4*>(&bias[nb * 64 + tx * 4]);
#pragma unroll
    for (int i = 0; i < 4; i++) {
        float4 o;
        o.x = acc[i][0] + bv.x; o.y = acc[i][1] + bv.y;
        o.z = acc[i][2] + bv.z; o.w = acc[i][3] + bv.w;
        *reinterpret_cast<float4*>(
            &gates[((size_t)t * Bq + ty * 4 + i) * Gq + nb * 64 + tx * 4]) = o;
    }
}

// ---------------- persistent recurrence: all 512 timesteps in one launch -----
// grid: 128 CTAs (cta = d*64 + q). Co-resident (128 <= 148 SMs), so a
// flag-array grid barrier is deadlock-free. Barrier phases are monotonic via
// g_epoch so graph replays / the second layer launch need no reset.
__global__ __launch_bounds__(256) void steps_k(
    const float* __restrict__ Whf, const float* __restrict__ Whb, int l)
{
    __shared__ float Wsm[16][64];
    __shared__ float Hsm[16][64];
    __shared__ float sg[64][64];

    int cta = blockIdx.x;
    int d = cta >> 6;
    int q = cta & 63;
    const float* Whh = d ? Whb : Whf;
    const float* pre = d ? g_gb : g_gf;
    float* hseq = l ? (d ? g_hb2 : g_hf2) : (d ? g_hb1 : g_hf1);
    float* cb = g_c + (size_t)d * Bq * Hq;

    int tid = threadIdx.x;
    int lm = tid >> 4, lk = tid & 15;
    int ty = lm, tx = lk;

    unsigned e = g_epoch;   // stable during this launch

    // activation-phase mapping
    int u = tid >> 4;
    int b0 = (tid & 15) * 4;
    int unit = q * 16 + u;

    for (int t = 0; t < Sq; t++) {
        float acc[4][4];
#pragma unroll
        for (int i = 0; i < 4; i++)
#pragma unroll
            for (int j = 0; j < 4; j++) acc[i][j] = 0.0f;

        if (t > 0) {
            const float* hprev = hseq + (size_t)(t - 1) * Bq * Hq;
            for (int k0 = 0; k0 < Hq; k0 += 16) {
#pragma unroll
                for (int i = 0; i < 4; i++) {
                    Wsm[lk][lm + i * 16] =
                        Whh[((size_t)i * Hq + q * 16 + lm) * Hq + k0 + lk];
                    Hsm[lk][lm + i * 16] =
                        hprev[(size_t)(lm + i * 16) * Hq + k0 + lk];
                }
                __syncthreads();
#pragma unroll
                for (int kk = 0; kk < 16; kk++) {
                    float4 wv = *reinterpret_cast<const float4*>(&Wsm[kk][ty * 4]);
                    float4 hv = *reinterpret_cast<const float4*>(&Hsm[kk][tx * 4]);
                    float w[4] = {wv.x, wv.y, wv.z, wv.w};
                    float h[4] = {hv.x, hv.y, hv.z, hv.w};
#pragma unroll
                    for (int i = 0; i < 4; i++)
#pragma unroll
                        for (int j = 0; j < 4; j++) acc[i][j] += w[i] * h[j];
                }
                __syncthreads();
            }
        }

        // stash GEMM result: sg[gate_row r][batch b]
#pragma unroll
        for (int i = 0; i < 4; i++) {
            float4 o;
            o.x = acc[i][0]; o.y = acc[i][1]; o.z = acc[i][2]; o.w = acc[i][3];
            *reinterpret_cast<float4*>(&sg[ty * 4 + i][tx * 4]) = o;
        }
        __syncthreads();

        // activations
#pragma unroll
        for (int jb = 0; jb < 4; jb++) {
            int b = b0 + jb;
            size_t prebase = ((size_t)t * Bq + b) * Gq + unit;
            float gi = sg[u][b]      + pre[prebase];
            float gf = sg[16 + u][b] + pre[prebase + Hq];
            float gg = sg[32 + u][b] + pre[prebase + 2 * Hq];
            float go = sg[48 + u][b] + pre[prebase + 3 * Hq];
            float si = sigf(gi);
            float sf = sigf(gf);
            float tg = tanhfast(gg);
            float so = sigf(go);
            float cold = (t == 0) ? 0.0f : cb[(size_t)b * Hq + unit];
            float cnew = sf * cold + si * tg;
            cb[(size_t)b * Hq + unit] = cnew;
            hseq[((size_t)t * Bq + b) * Hq + unit] = so * tanhfast(cnew);
        }

        // ---- grid barrier (release h(t) to all CTAs) ----
        __syncthreads();
        __threadfence();
        if (tid == 0) g_flags[cta] = e + t + 1;
        if (tid < 128) {
            unsigned tgt = e + t + 1;
            while (g_flags[tid] < tgt) __nanosleep(64);
        }
        __syncthreads();
    }

    if (cta == 0 && tid == 0) g_epoch = e + Sq;
}

// ---------------- output GEMM: out = concat(f, r_rev) @ Wout^T + bout --------
__global__ __launch_bounds__(256) void outgemm_k(
    const float* __restrict__ Wout, const float* __restrict__ bout,
    float* __restrict__ out)
{
    __shared__ float As[16][64];
    __shared__ float Ws[16][64];
    int s = blockIdx.x;
    int tid = threadIdx.x;
    int lm = tid >> 4, lk = tid & 15;
    int ty = lm, tx = lk;

    const float* fbase = g_hf2 + (size_t)s * Bq * Hq;
    const float* rbase = g_hb2 + (size_t)(Sq - 1 - s) * Bq * Hq;

    float acc[4][4];
#pragma unroll
    for (int i = 0; i < 4; i++)
#pragma unroll
        for (int j = 0; j < 4; j++) acc[i][j] = 0.0f;

    for (int k0 = 0; k0 < KOUT; k0 += 16) {
        const float* A = (k0 < Hq) ? fbase : rbase;
        int ka = (k0 < Hq) ? k0 : (k0 - Hq);
#pragma unroll
        for (int i = 0; i < 4; i++) {
            As[lk][lm + i * 16] = A[(size_t)(lm + i * 16) * Hq + ka + lk];
            int n = lm + i * 16;
            Ws[lk][lm + i * 16] = (n < Oq) ? Wout[(size_t)n * KOUT + k0 + lk] : 0.0f;
        }
        __syncthreads();
#pragma unroll
        for (int kk = 0; kk < 16; kk++) {
            float4 av = *reinterpret_cast<const float4*>(&As[kk][ty * 4]);
            float4 wv = *reinterpret_cast<const float4*>(&Ws[kk][tx * 4]);
            float a[4] = {av.x, av.y, av.z, av.w};
            float w[4] = {wv.x, wv.y, wv.z, wv.w};
#pragma unroll
            for (int i = 0; i < 4; i++)
#pragma unroll
                for (int j = 0; j < 4; j++) acc[i][j] += a[i] * w[j];
        }
        __syncthreads();
    }

#pragma unroll
    for (int i = 0; i < 4; i++) {
        int b = ty * 4 + i;
#pragma unroll
        for (int j = 0; j < 4; j++) {
            int n = tx * 4 + j;
            if (n < Oq)
                out[((size_t)b * Sq + s) * Oq + n] = acc[i][j] + bout[n];
        }
    }
}

// ---------------- launcher ----------------------------------------------------
extern "C" void kernel_launch(void* const* d_in, const int* in_sizes, int n_in,
                              void* d_out, int out_size)
{
    const int*   src   = (const int*)  d_in[0];
    const float* emb   = (const float*)d_in[1];
    const float* Wih_f = (const float*)d_in[2];
    const float* Whh_f = (const float*)d_in[3];
    const float* b_f   = (const float*)d_in[4];
    const float* Wih_b = (const float*)d_in[5];
    const float* Whh_b = (const float*)d_in[6];
    const float* b_b   = (const float*)d_in[7];
    const float* Wout  = (const float*)d_in[8];
    const float* bout  = (const float*)d_in[9];
    float* out = (float*)d_out;

    embed_k<<<Sq * Bq, 256>>>(src, emb);

    for (int l = 0; l < 2; l++) {
        pregemm_k<<<dim3(64, Sq), 256>>>(
            (l == 0) ? 0 : 1, Wih_f + (size_t)l * Gq * Eq, b_f + l * Gq, 0, 0);
        pregemm_k<<<dim3(64, Sq), 256>>>(
            (l == 0) ? 0 : 2, Wih_b + (size_t)l * Gq * Eq, b_b + l * Gq, 1,
            (l == 0) ? 1 : 0);

        steps_k<<<128, 256>>>(
            Whh_f + (size_t)l * Gq * Hq, Whh_b + (size_t)l * Gq * Hq, l);
    }

    outgemm_k<<<Sq, 256>>>(Wout, bout, out);
}

// round 8
// speedup vs baseline: 1.4345x; 1.4345x over previous
#include <cuda_runtime.h>
#include <cstdint>

// Problem constants
#define Bq 64
#define Sq 512
#define Eq 1024
#define Hq 1024
#define Gq 4096     // 4*H
#define Oq 50
#define KOUT 2048   // 2*H

// ---------------- scratch (device globals; no runtime allocation) ----------
__device__ float g_x  [(size_t)Sq*Bq*Eq];   // embedded input, (S,B,E)
__device__ float g_hf1[(size_t)Sq*Bq*Hq];   // fwd layer-1 output (S,B,H)
__device__ float g_hb1[(size_t)Sq*Bq*Hq];   // bwd layer-1 output (u=reversed time)
__device__ float g_hf2[(size_t)Sq*Bq*Hq];   // fwd layer-2 output
__device__ float g_hb2[(size_t)Sq*Bq*Hq];   // bwd layer-2 output (u order)
__device__ float g_gf [(size_t)Sq*Bq*Gq];   // fwd pre-gates for current layer
__device__ float g_gb [(size_t)Sq*Bq*Gq];   // bwd pre-gates for current layer
__device__ float g_c  [2*Bq*Hq];            // cell state per direction

// grid-barrier state (monotonic across launches & graph replays)
__device__ volatile unsigned g_flags[128];
__device__ unsigned g_epoch = 0;

// ---------------- helpers ---------------------------------------------------
__device__ __forceinline__ float sigf(float x) {
    return __fdividef(1.0f, 1.0f + __expf(-x));
}
__device__ __forceinline__ float tanhfast(float x) {
    return __fdividef(2.0f, 1.0f + __expf(-2.0f * x)) - 1.0f;
}

// round fp32 -> tf32 (rna), keep in fp32 container
__device__ __forceinline__ float tf32r(float x) {
    uint32_t u;
    asm("cvt.rna.tf32.f32 %0, %1;" : "=r"(u) : "f"(x));
    return __uint_as_float(u);
}

// D(16x8,f32) += A(16x8,tf32,row) * B(8x8,tf32,col)
__device__ __forceinline__ void mma_tf32(float* d, const float* a, float b0f, float b1f) {
    asm volatile(
        "mma.sync.aligned.m16n8k8.row.col.f32.tf32.tf32.f32 "
        "{%0,%1,%2,%3}, {%4,%5,%6,%7}, {%8,%9}, {%0,%1,%2,%3};"
        : "+f"(d[0]), "+f"(d[1]), "+f"(d[2]), "+f"(d[3])
        : "r"(__float_as_uint(a[0])), "r"(__float_as_uint(a[1])),
          "r"(__float_as_uint(a[2])), "r"(__float_as_uint(a[3])),
          "r"(__float_as_uint(b0f)), "r"(__float_as_uint(b1f)));
}

// ---------------- embedding gather ------------------------------------------
__global__ void embed_k(const int* __restrict__ src, const float* __restrict__ emb) {
    int row = blockIdx.x;           // s*B + b
    int s = row >> 6;
    int b = row & 63;
    int v = src[b * Sq + s];
    const float4* e4 = reinterpret_cast<const float4*>(emb + (size_t)v * Eq);
    float4* d4 = reinterpret_cast<float4*>(g_x + (size_t)row * Eq);
    d4[threadIdx.x] = e4[threadIdx.x];
}

// ---------------- tf32 mma.sync pre-gates GEMM -------------------------------
// gates[m][n] = sum_k in[row(m)][k] * W[n][k] + bias[n]
// m = t*64+b; time reversal (rev) applied on the A read only.
// CTA 128x128, 8 warps in 4(M)x2(N), warp tile 32x64, mma m16n8k8 tf32.
// grid: (Gq/128=32, 32768/128=256), 256 threads.
__global__ __launch_bounds__(256) void pregemm_mma(
    int insel, const float* __restrict__ W0, const float* __restrict__ bias,
    int dirout, int rev)
{
    __shared__ float As[128][36];
    __shared__ float Ws[128][36];
    __shared__ float s_bias[128];

    const float* in = (insel == 0) ? g_x : ((insel == 1) ? g_hf1 : g_hb1);
    float* gates = dirout ? g_gb : g_gf;

    const int n0 = blockIdx.x * 128;
    const int m0 = blockIdx.y * 128;
    const int tid = threadIdx.x;
    const int wid = tid >> 5;
    const int lane = tid & 31;
    const int warp_m = wid & 3;          // 32-row block
    const int warp_n = wid >> 2;         // 64-col block
    const int g = lane >> 2;
    const int c = lane & 3;

    if (tid < 128) s_bias[tid] = bias[n0 + tid];

    // load mapping: thread covers row tr, 4 float4 at cols tc*16 + j*4
    const int tr = tid >> 1;
    const int tc = tid & 1;
    {
    }
    const int m_in = m0 + tr;
    const int t_in = m_in >> 6, b_in = m_in & 63;
    const int tin = rev ? (Sq - 1 - t_in) : t_in;
    const float* aptr = in + ((size_t)tin * Bq + b_in) * Eq + tc * 16;
    const float* wptr = W0 + (size_t)(n0 + tr) * Eq + tc * 16;

    float acc[2][8][4];
#pragma unroll
    for (int mt = 0; mt < 2; mt++)
#pragma unroll
        for (int nt = 0; nt < 8; nt++)
#pragma unroll
            for (int r = 0; r < 4; r++) acc[mt][nt][r] = 0.0f;

    float4 ra[4], rw[4];
#pragma unroll
    for (int j = 0; j < 4; j++) {
        ra[j] = *reinterpret_cast<const float4*>(aptr + j * 4);
        rw[j] = *reinterpret_cast<const float4*>(wptr + j * 4);
    }

    for (int kc = 0; kc < Eq / 32; kc++) {
        __syncthreads();   // previous iteration's consumers are done
#pragma unroll
        for (int j = 0; j < 4; j++) {
            float4 va, vw;
            va.x = tf32r(ra[j].x); va.y = tf32r(ra[j].y);
            va.z = tf32r(ra[j].z); va.w = tf32r(ra[j].w);
            vw.x = tf32r(rw[j].x); vw.y = tf32r(rw[j].y);
            vw.z = tf32r(rw[j].z); vw.w = tf32r(rw[j].w);
            *reinterpret_cast<float4*>(&As[tr][tc * 16 + j * 4]) = va;
            *reinterpret_cast<float4*>(&Ws[tr][tc * 16 + j * 4]) = vw;
        }
        if (kc + 1 < Eq / 32) {
            int koff = (kc + 1) * 32;
#pragma unroll
            for (int j = 0; j < 4; j++) {
                ra[j] = *reinterpret_cast<const float4*>(aptr + koff + j * 4);
                rw[j] = *reinterpret_cast<const float4*>(wptr + koff + j * 4);
            }
        }
        __syncthreads();

#pragma unroll
        for (int ks = 0; ks < 4; ks++) {
            const int kb = ks * 8;
            float a[2][4];
#pragma unroll
            for (int mt = 0; mt < 2; mt++) {
                int row = warp_m * 32 + mt * 16;
                a[mt][0] = As[row + g][kb + c];
                a[mt][1] = As[row + 8 + g][kb + c];
                a[mt][2] = As[row + g][kb + c + 4];
                a[mt][3] = As[row + 8 + g][kb + c + 4];
            }
#pragma unroll
            for (int nt = 0; nt < 8; nt++) {
                int nb = warp_n * 64 + nt * 8;
                float b0 = Ws[nb + g][kb + c];
                float b1 = Ws[nb + g][kb + c + 4];
                mma_tf32(acc[0][nt], a[0], b0, b1);
                mma_tf32(acc[1][nt], a[1], b0, b1);
            }
        }
    }

    // epilogue: D row = warp_m*32 + mt*16 + g (+8), col = warp_n*64 + nt*8 + c*2 (+1)
#pragma unroll
    for (int mt = 0; mt < 2; mt++) {
        int r0 = m0 + warp_m * 32 + mt * 16 + g;
#pragma unroll
        for (int nt = 0; nt < 8; nt++) {
            int col = warp_n * 64 + nt * 8 + c * 2;
            float2 v0, v1;
            v0.x = acc[mt][nt][0] + s_bias[col];
            v0.y = acc[mt][nt][1] + s_bias[col + 1];
            v1.x = acc[mt][nt][2] + s_bias[col];
            v1.y = acc[mt][nt][3] + s_bias[col + 1];
            *reinterpret_cast<float2*>(&gates[(size_t)r0 * Gq + n0 + col]) = v0;
            *reinterpret_cast<float2*>(&gates[(size_t)(r0 + 8) * Gq + n0 + col]) = v1;
        }
    }
}

// ---------------- persistent recurrence: all 512 timesteps in one launch -----
__global__ __launch_bounds__(256) void steps_k(
    const float* __restrict__ Whf, const float* __restrict__ Whb, int l)
{
    __shared__ float Wsm[16][64];
    __shared__ float Hsm[16][64];
    __shared__ float sg[64][64];

    int cta = blockIdx.x;
    int d = cta >> 6;
    int q = cta & 63;
    const float* Whh = d ? Whb : Whf;
    const float* pre = d ? g_gb : g_gf;
    float* hseq = l ? (d ? g_hb2 : g_hf2) : (d ? g_hb1 : g_hf1);
    float* cb = g_c + (size_t)d * Bq * Hq;

    int tid = threadIdx.x;
    int lm = tid >> 4, lk = tid & 15;
    int ty = lm, tx = lk;

    unsigned e = g_epoch;

    int u = tid >> 4;
    int b0 = (tid & 15) * 4;
    int unit = q * 16 + u;

    for (int t = 0; t < Sq; t++) {
        float acc[4][4];
#pragma unroll
        for (int i = 0; i < 4; i++)
#pragma unroll
            for (int j = 0; j < 4; j++) acc[i][j] = 0.0f;

        if (t > 0) {
            const float* hprev = hseq + (size_t)(t - 1) * Bq * Hq;
            for (int k0 = 0; k0 < Hq; k0 += 16) {
#pragma unroll
                for (int i = 0; i < 4; i++) {
                    Wsm[lk][lm + i * 16] =
                        Whh[((size_t)i * Hq + q * 16 + lm) * Hq + k0 + lk];
                    Hsm[lk][lm + i * 16] =
                        hprev[(size_t)(lm + i * 16) * Hq + k0 + lk];
                }
                __syncthreads();
#pragma unroll
                for (int kk = 0; kk < 16; kk++) {
                    float4 wv = *reinterpret_cast<const float4*>(&Wsm[kk][ty * 4]);
                    float4 hv = *reinterpret_cast<const float4*>(&Hsm[kk][tx * 4]);
                    float w[4] = {wv.x, wv.y, wv.z, wv.w};
                    float h[4] = {hv.x, hv.y, hv.z, hv.w};
#pragma unroll
                    for (int i = 0; i < 4; i++)
#pragma unroll
                        for (int j = 0; j < 4; j++) acc[i][j] += w[i] * h[j];
                }
                __syncthreads();
            }
        }

#pragma unroll
        for (int i = 0; i < 4; i++) {
            float4 o;
            o.x = acc[i][0]; o.y = acc[i][1]; o.z = acc[i][2]; o.w = acc[i][3];
            *reinterpret_cast<float4*>(&sg[ty * 4 + i][tx * 4]) = o;
        }
        __syncthreads();

#pragma unroll
        for (int jb = 0; jb < 4; jb++) {
            int b = b0 + jb;
            size_t prebase = ((size_t)t * Bq + b) * Gq + unit;
            float gi = sg[u][b]      + pre[prebase];
            float gf = sg[16 + u][b] + pre[prebase + Hq];
            float gg = sg[32 + u][b] + pre[prebase + 2 * Hq];
            float go = sg[48 + u][b] + pre[prebase + 3 * Hq];
            float si = sigf(gi);
            float sf = sigf(gf);
            float tg = tanhfast(gg);
            float so = sigf(go);
            float cold = (t == 0) ? 0.0f : cb[(size_t)b * Hq + unit];
            float cnew = sf * cold + si * tg;
            cb[(size_t)b * Hq + unit] = cnew;
            hseq[((size_t)t * Bq + b) * Hq + unit] = so * tanhfast(cnew);
        }

        __syncthreads();
        __threadfence();
        if (tid == 0) g_flags[cta] = e + t + 1;
        if (tid < 128) {
            unsigned tgt = e + t + 1;
            while (g_flags[tid] < tgt) __nanosleep(64);
        }
        __syncthreads();
    }

    if (cta == 0 && tid == 0) g_epoch = e + Sq;
}

// ---------------- output GEMM: out = concat(f, r_rev) @ Wout^T + bout --------
__global__ __launch_bounds__(256) void outgemm_k(
    const float* __restrict__ Wout, const float* __restrict__ bout,
    float* __restrict__ out)
{
    __shared__ float As[16][64];
    __shared__ float Ws[16][64];
    int s = blockIdx.x;
    int tid = threadIdx.x;
    int lm = tid >> 4, lk = tid & 15;
    int ty = lm, tx = lk;

    const float* fbase = g_hf2 + (size_t)s * Bq * Hq;
    const float* rbase = g_hb2 + (size_t)(Sq - 1 - s) * Bq * Hq;

    float acc[4][4];
#pragma unroll
    for (int i = 0; i < 4; i++)
#pragma unroll
        for (int j = 0; j < 4; j++) acc[i][j] = 0.0f;

    for (int k0 = 0; k0 < KOUT; k0 += 16) {
        const float* A = (k0 < Hq) ? fbase : rbase;
        int ka = (k0 < Hq) ? k0 : (k0 - Hq);
#pragma unroll
        for (int i = 0; i < 4; i++) {
            As[lk][lm + i * 16] = A[(size_t)(lm + i * 16) * Hq + ka + lk];
            int n = lm + i * 16;
            Ws[lk][lm + i * 16] = (n < Oq) ? Wout[(size_t)n * KOUT + k0 + lk] : 0.0f;
        }
        __syncthreads();
#pragma unroll
        for (int kk = 0; kk < 16; kk++) {
            float4 av = *reinterpret_cast<const float4*>(&As[kk][ty * 4]);
            float4 wv = *reinterpret_cast<const float4*>(&Ws[kk][tx * 4]);
            float a[4] = {av.x, av.y, av.z, av.w};
            float w[4] = {wv.x, wv.y, wv.z, wv.w};
#pragma unroll
            for (int i = 0; i < 4; i++)
#pragma unroll
                for (int j = 0; j < 4; j++) acc[i][j] += a[i] * w[j];
        }
        __syncthreads();
    }

#pragma unroll
    for (int i = 0; i < 4; i++) {
        int b = ty * 4 + i;
#pragma unroll
        for (int j = 0; j < 4; j++) {
            int n = tx * 4 + j;
            if (n < Oq)
                out[((size_t)b * Sq + s) * Oq + n] = acc[i][j] + bout[n];
        }
    }
}

// ---------------- launcher ----------------------------------------------------
extern "C" void kernel_launch(void* const* d_in, const int* in_sizes, int n_in,
                              void* d_out, int out_size)
{
    const int*   src   = (const int*)  d_in[0];
    const float* emb   = (const float*)d_in[1];
    const float* Wih_f = (const float*)d_in[2];
    const float* Whh_f = (const float*)d_in[3];
    const float* b_f   = (const float*)d_in[4];
    const float* Wih_b = (const float*)d_in[5];
    const float* Whh_b = (const float*)d_in[6];
    const float* b_b   = (const float*)d_in[7];
    const float* Wout  = (const float*)d_in[8];
    const float* bout  = (const float*)d_in[9];
    float* out = (float*)d_out;

    embed_k<<<Sq * Bq, 256>>>(src, emb);

    for (int l = 0; l < 2; l++) {
        pregemm_mma<<<dim3(32, 256), 256>>>(
            (l == 0) ? 0 : 1, Wih_f + (size_t)l * Gq * Eq, b_f + l * Gq, 0, 0);
        pregemm_mma<<<dim3(32, 256), 256>>>(
            (l == 0) ? 0 : 2, Wih_b + (size_t)l * Gq * Eq, b_b + l * Gq, 1,
            (l == 0) ? 1 : 0);

        steps_k<<<128, 256>>>(
            Whh_f + (size_t)l * Gq * Hq, Whh_b + (size_t)l * Gq * Hq, l);
    }

    outgemm_k<<<Sq, 256>>>(Wout, bout, out);
}

// round 10
// speedup vs baseline: 4.7066x; 3.2811x over previous
#include <cuda_runtime.h>
#include <cstdint>

// Problem constants
#define Bq 64
#define Sq 512
#define Eq 1024
#define Hq 1024
#define Gq 4096     // 4*H
#define Oq 50
#define KOUT 2048   // 2*H

// ---------------- scratch (device globals; no runtime allocation) ----------
__device__ float g_x  [(size_t)Sq*Bq*Eq];   // embedded input, (S,B,E)
__device__ float g_hf1[(size_t)Sq*Bq*Hq];   // fwd layer-1 output (S,B,H)
__device__ float g_hb1[(size_t)Sq*Bq*Hq];   // bwd layer-1 output (u=reversed time)
__device__ float g_hf2[(size_t)Sq*Bq*Hq];   // fwd layer-2 output
__device__ float g_hb2[(size_t)Sq*Bq*Hq];   // bwd layer-2 output (u order)
__device__ float g_gf [(size_t)Sq*Bq*Gq];   // fwd pre-gates for current layer
__device__ float g_gb [(size_t)Sq*Bq*Gq];   // bwd pre-gates for current layer
__device__ float g_wh [(size_t)2*Gq*Hq];    // tf32-rounded Whh (both dirs, current layer)

// grid-barrier state (monotonic across launches & graph replays)
__device__ volatile unsigned g_flags[128];
__device__ unsigned g_epoch = 0;

// ---------------- helpers ---------------------------------------------------
__device__ __forceinline__ float sigf(float x) {
    return __fdividef(1.0f, 1.0f + __expf(-x));
}
__device__ __forceinline__ float tanhfast(float x) {
    return __fdividef(2.0f, 1.0f + __expf(-2.0f * x)) - 1.0f;
}

// round fp32 -> tf32 (rna), keep in fp32 container
__device__ __forceinline__ float tf32r(float x) {
    uint32_t u;
    asm("cvt.rna.tf32.f32 %0, %1;" : "=r"(u) : "f"(x));
    return __uint_as_float(u);
}

__device__ __forceinline__ uint32_t smem_u32(const void* p) {
    uint32_t a;
    asm("{ .reg .u64 t; cvta.to.shared.u64 t, %1; cvt.u32.u64 %0, t; }"
        : "=r"(a) : "l"(p));
    return a;
}

// D(16x8,f32) += A(16x8,tf32,row) * B(8x8,tf32,col)
__device__ __forceinline__ void mma_tf32(float* d, const float* a, float b0f, float b1f) {
    asm volatile(
        "mma.sync.aligned.m16n8k8.row.col.f32.tf32.tf32.f32 "
        "{%0,%1,%2,%3}, {%4,%5,%6,%7}, {%8,%9}, {%0,%1,%2,%3};"
        : "+f"(d[0]), "+f"(d[1]), "+f"(d[2]), "+f"(d[3])
        : "r"(__float_as_uint(a[0])), "r"(__float_as_uint(a[1])),
          "r"(__float_as_uint(a[2])), "r"(__float_as_uint(a[3])),
          "r"(__float_as_uint(b0f)), "r"(__float_as_uint(b1f)));
}

#define CP16(dst, src) \
    asm volatile("cp.async.cg.shared.global [%0], [%1], 16;" \
                 :: "r"(dst), "l"(src) : "memory")
#define CPCOMMIT() asm volatile("cp.async.commit_group;" ::: "memory")
#define CPWAIT(n)  asm volatile("cp.async.wait_group " #n ";" ::: "memory")

// ---------------- embedding gather ------------------------------------------
__global__ void embed_k(const int* __restrict__ src, const float* __restrict__ emb) {
    int row = blockIdx.x;           // s*B + b
    int s = row >> 6;
    int b = row & 63;
    int v = src[b * Sq + s];
    const float4* e4 = reinterpret_cast<const float4*>(emb + (size_t)v * Eq);
    float4* d4 = reinterpret_cast<float4*>(g_x + (size_t)row * Eq);
    d4[threadIdx.x] = e4[threadIdx.x];
}

// ---------------- Whh tf32 pre-round (per layer) -----------------------------
__global__ void whround_k(const float* __restrict__ Wf, const float* __restrict__ Wb) {
    size_t i = (size_t)blockIdx.x * blockDim.x + threadIdx.x;   // float4 index
    const size_t NF = (size_t)Gq * Hq / 4;
    float4 v;
    float4* dst = reinterpret_cast<float4*>(g_wh);
    if (i < NF) v = reinterpret_cast<const float4*>(Wf)[i];
    else        v = reinterpret_cast<const float4*>(Wb)[i - NF];
    v.x = tf32r(v.x); v.y = tf32r(v.y); v.z = tf32r(v.z); v.w = tf32r(v.w);
    dst[i] = v;
}

// ---------------- tf32 mma.sync pre-gates GEMM -------------------------------
// gates[m][n] = sum_k in[row(m)][k] * W[n][k] + bias[n]
__global__ __launch_bounds__(256) void pregemm_mma(
    int insel, const float* __restrict__ W0, const float* __restrict__ bias,
    int dirout, int rev)
{
    __shared__ float As[128][36];
    __shared__ float Ws[128][36];
    __shared__ float s_bias[128];

    const float* in = (insel == 0) ? g_x : ((insel == 1) ? g_hf1 : g_hb1);
    float* gates = dirout ? g_gb : g_gf;

    const int n0 = blockIdx.x * 128;
    const int m0 = blockIdx.y * 128;
    const int tid = threadIdx.x;
    const int wid = tid >> 5;
    const int lane = tid & 31;
    const int warp_m = wid & 3;
    const int warp_n = wid >> 2;
    const int g = lane >> 2;
    const int c = lane & 3;

    if (tid < 128) s_bias[tid] = bias[n0 + tid];

    const int tr = tid >> 1;
    const int tc = tid & 1;
    const int m_in = m0 + tr;
    const int t_in = m_in >> 6, b_in = m_in & 63;
    const int tin = rev ? (Sq - 1 - t_in) : t_in;
    const float* aptr = in + ((size_t)tin * Bq + b_in) * Eq + tc * 16;
    const float* wptr = W0 + (size_t)(n0 + tr) * Eq + tc * 16;

    float acc[2][8][4];
#pragma unroll
    for (int mt = 0; mt < 2; mt++)
#pragma unroll
        for (int nt = 0; nt < 8; nt++)
#pragma unroll
            for (int r = 0; r < 4; r++) acc[mt][nt][r] = 0.0f;

    float4 ra[4], rw[4];
#pragma unroll
    for (int j = 0; j < 4; j++) {
        ra[j] = *reinterpret_cast<const float4*>(aptr + j * 4);
        rw[j] = *reinterpret_cast<const float4*>(wptr + j * 4);
    }

    for (int kc = 0; kc < Eq / 32; kc++) {
        __syncthreads();
#pragma unroll
        for (int j = 0; j < 4; j++) {
            float4 va, vw;
            va.x = tf32r(ra[j].x); va.y = tf32r(ra[j].y);
            va.z = tf32r(ra[j].z); va.w = tf32r(ra[j].w);
            vw.x = tf32r(rw[j].x); vw.y = tf32r(rw[j].y);
            vw.z = tf32r(rw[j].z); vw.w = tf32r(rw[j].w);
            *reinterpret_cast<float4*>(&As[tr][tc * 16 + j * 4]) = va;
            *reinterpret_cast<float4*>(&Ws[tr][tc * 16 + j * 4]) = vw;
        }
        if (kc + 1 < Eq / 32) {
            int koff = (kc + 1) * 32;
#pragma unroll
            for (int j = 0; j < 4; j++) {
                ra[j] = *reinterpret_cast<const float4*>(aptr + koff + j * 4);
                rw[j] = *reinterpret_cast<const float4*>(wptr + koff + j * 4);
            }
        }
        __syncthreads();

#pragma unroll
        for (int ks = 0; ks < 4; ks++) {
            const int kb = ks * 8;
            float a[2][4];
#pragma unroll
            for (int mt = 0; mt < 2; mt++) {
                int row = warp_m * 32 + mt * 16;
                a[mt][0] = As[row + g][kb + c];
                a[mt][1] = As[row + 8 + g][kb + c];
                a[mt][2] = As[row + g][kb + c + 4];
                a[mt][3] = As[row + 8 + g][kb + c + 4];
            }
#pragma unroll
            for (int nt = 0; nt < 8; nt++) {
                int nb = warp_n * 64 + nt * 8;
                float b0 = Ws[nb + g][kb + c];
                float b1 = Ws[nb + g][kb + c + 4];
                mma_tf32(acc[0][nt], a[0], b0, b1);
                mma_tf32(acc[1][nt], a[1], b0, b1);
            }
        }
    }

#pragma unroll
    for (int mt = 0; mt < 2; mt++) {
        int r0 = m0 + warp_m * 32 + mt * 16 + g;
#pragma unroll
        for (int nt = 0; nt < 8; nt++) {
            int col = warp_n * 64 + nt * 8 + c * 2;
            float2 v0, v1;
            v0.x = acc[mt][nt][0] + s_bias[col];
            v0.y = acc[mt][nt][1] + s_bias[col + 1];
            v1.x = acc[mt][nt][2] + s_bias[col];
            v1.y = acc[mt][nt][3] + s_bias[col + 1];
            *reinterpret_cast<float2*>(&gates[(size_t)r0 * Gq + n0 + col]) = v0;
            *reinterpret_cast<float2*>(&gates[(size_t)(r0 + 8) * Gq + n0 + col]) = v1;
        }
    }
}

// ---------------- persistent tensor-core recurrence --------------------------
// 128 CTAs (cta = d*64 + q), 128 threads. CTA computes per step:
//   gates(64 batch x 64 gate-rows {g*1024+q*16+u}) += h(t-1) @ Whh^T  (tf32 mma)
// then activations + state update. Whh pre-rounded in g_wh; h written
// tf32-rounded so no cvt in the hot loop. Cell state lives in SMEM.
#define STR 68
#define ABUF (64 * STR)   // floats per chunk buffer (4352)
// float-offset layout in dynamic smem:
//   A0=0, A1=ABUF, B0=2*ABUF, B1=3*ABUF, SG=4*ABUF (64x65),
//   PRE=SG+4160 (64x64), CS=PRE+4096 (16x65), HS=CS+1040 (64x16)
#define SG_OFF   (4 * ABUF)
#define PRE_OFF  (SG_OFF + 64 * 65)
#define CS_OFF   (PRE_OFF + 64 * 64)
#define HS_OFF   (CS_OFF + 16 * 65)
#define SMEM_ST_FLOATS (HS_OFF + 64 * 16)
#define SMEM_ST_BYTES  (SMEM_ST_FLOATS * 4)

__global__ __launch_bounds__(128) void steps2_k(int l)
{
    extern __shared__ float smf[];
    float* sg    = smf + SG_OFF;
    float* pre_s = smf + PRE_OFF;
    float* c_s   = smf + CS_OFF;
    float* h_s   = smf + HS_OFF;

    const int cta = blockIdx.x;
    const int d = cta >> 6;
    const int q = cta & 63;
    const float* pre = d ? g_gb : g_gf;
    const float* whb = g_wh + (size_t)d * Gq * Hq;
    float* hseq = l ? (d ? g_hb2 : g_hf2) : (d ? g_hb1 : g_hf1);

    const int tid = threadIdx.x;
    const int wid = tid >> 5;
    const int lane = tid & 31;
    const int warp_m = wid & 1;
    const int warp_n = wid >> 1;
    const int g_ = lane >> 2;
    const int c_ = lane & 3;

    const uint32_t sbase = smem_u32(smf);

    // per-thread cp.async constants: row_j = (tid>>4) + 8j, col16 = tid&15
    const int r0 = tid >> 4;
    const int c16 = tid & 15;
    const float* wrow[8];
#pragma unroll
    for (int j = 0; j < 8; j++) {
        int r = r0 + 8 * j;
        int gr = (r >> 4) * 1024 + q * 16 + (r & 15);
        wrow[j] = whb + (size_t)gr * Hq + c16 * 4;
    }

    const unsigned e = g_epoch;

    for (int i = tid; i < 16 * 65; i += 128) c_s[i] = 0.0f;
    __syncthreads();

    const int u = tid & 15;          // local unit
    const int bg = tid >> 4;         // batch group

    for (int t = 0; t < Sq; t++) {
        // stage pre-gates for this step (own cp.async group)
#pragma unroll
        for (int j = 0; j < 8; j++) {
            int idx = tid + j * 128;
            int b = idx >> 4, rem = idx & 15;
            int gg = rem >> 2, qt = rem & 3;
            const float* src = pre + ((size_t)t * Bq + b) * Gq + gg * 1024 + q * 16 + qt * 4;
            uint32_t dst = sbase + (uint32_t)((PRE_OFF + b * 64 + gg * 16 + qt * 4) * 4);
            CP16(dst, src);
        }
        CPCOMMIT();

        float acc[2][4][4];
#pragma unroll
        for (int mt = 0; mt < 2; mt++)
#pragma unroll
            for (int nt = 0; nt < 4; nt++)
#pragma unroll
                for (int r = 0; r < 4; r++) acc[mt][nt][r] = 0.0f;

        if (t > 0) {
            const float* hprev = hseq + (size_t)(t - 1) * Bq * Hq;
            auto issue = [&](int ic) {
                int k0 = ic * 64;
                uint32_t abase = sbase + (uint32_t)(((ic & 1) ? ABUF : 0) * 4);
                uint32_t bbase = abase + (uint32_t)(2 * ABUF * 4);
#pragma unroll
                for (int j = 0; j < 8; j++) {
                    int r = r0 + 8 * j;
                    const float* asrc = hprev + (size_t)r * Hq + k0 + c16 * 4;
                    CP16(abase + (uint32_t)((r * STR + c16 * 4) * 4), asrc);
                    const float* bsrc = wrow[j] + k0;
                    CP16(bbase + (uint32_t)((r * STR + c16 * 4) * 4), bsrc);
                }
            };
            issue(0);
            CPCOMMIT();
            for (int ic = 0; ic < 16; ic++) {
                if (ic + 1 < 16) { issue(ic + 1); CPCOMMIT(); CPWAIT(1); }
                else             { CPWAIT(0); }
                __syncthreads();
                const float* Asm = smf + ((ic & 1) ? ABUF : 0);
                const float* Bsm = Asm + 2 * ABUF;
#pragma unroll
                for (int ks = 0; ks < 8; ks++) {
                    const int kb = ks * 8;
                    float a[2][4];
#pragma unroll
                    for (int mt = 0; mt < 2; mt++) {
                        int rr = warp_m * 32 + mt * 16;
                        a[mt][0] = Asm[(rr + g_) * STR + kb + c_];
                        a[mt][1] = Asm[(rr + 8 + g_) * STR + kb + c_];
                        a[mt][2] = Asm[(rr + g_) * STR + kb + c_ + 4];
                        a[mt][3] = Asm[(rr + 8 + g_) * STR + kb + c_ + 4];
                    }
#pragma unroll
                    for (int nt = 0; nt < 4; nt++) {
                        int nb = warp_n * 32 + nt * 8;
                        float b0 = Bsm[(nb + g_) * STR + kb + c_];
                        float b1 = Bsm[(nb + g_) * STR + kb + c_ + 4];
                        mma_tf32(acc[0][nt], a[0], b0, b1);
                        mma_tf32(acc[1][nt], a[1], b0, b1);
                    }
                }
                __syncthreads();
            }
        } else {
            CPWAIT(0);
            __syncthreads();
        }

        // acc -> sg[n_local][batch]  (D row = batch m, col = gate row n)
#pragma unroll
        for (int mt = 0; mt < 2; mt++) {
            int ml = warp_m * 32 + mt * 16 + g_;
#pragma unroll
            for (int nt = 0; nt < 4; nt++) {
                int nl = warp_n * 32 + nt * 8 + c_ * 2;
                sg[nl * 65 + ml]           = acc[mt][nt][0];
                sg[(nl + 1) * 65 + ml]     = acc[mt][nt][1];
                sg[nl * 65 + ml + 8]       = acc[mt][nt][2];
                sg[(nl + 1) * 65 + ml + 8] = acc[mt][nt][3];
            }
        }
        __syncthreads();

        // activations: thread = (unit u, batch group bg), 8 batches
#pragma unroll
        for (int j = 0; j < 8; j++) {
            int b = bg * 8 + j;
            float gi = sg[u * 65 + b]        + pre_s[b * 64 + u];
            float gf = sg[(16 + u) * 65 + b] + pre_s[b * 64 + 16 + u];
            float gg = sg[(32 + u) * 65 + b] + pre_s[b * 64 + 32 + u];
            float go = sg[(48 + u) * 65 + b] + pre_s[b * 64 + 48 + u];
            float cold = c_s[u * 65 + b];
            float cnew = sigf(gf) * cold + sigf(gi) * tanhfast(gg);
            c_s[u * 65 + b] = cnew;
            h_s[b * 16 + u] = tf32r(sigf(go) * tanhfast(cnew));
        }
        __syncthreads();

        // coalesced STG of h(t)
#pragma unroll
        for (int r = 0; r < 2; r++) {
            int idx = tid + r * 128;
            int b = idx >> 2, qt = idx & 3;
            float4 v = *reinterpret_cast<const float4*>(&h_s[b * 16 + qt * 4]);
            *reinterpret_cast<float4*>(
                &hseq[((size_t)t * Bq + b) * Hq + q * 16 + qt * 4]) = v;
        }

        // per-direction grid barrier (release h(t))
        __syncthreads();
        __threadfence();
        if (tid == 0) g_flags[cta] = e + t + 1;
        if (tid < 64) {
            unsigned tgt = e + t + 1;
            while (g_flags[d * 64 + tid] < tgt) __nanosleep(64);
        }
        __syncthreads();
    }

    if (cta == 0 && tid == 0) g_epoch = e + Sq;
}

// ---------------- output GEMM: out = concat(f, r_rev) @ Wout^T + bout --------
__global__ __launch_bounds__(256) void outgemm_k(
    const float* __restrict__ Wout, const float* __restrict__ bout,
    float* __restrict__ out)
{
    __shared__ float As[16][64];
    __shared__ float Ws[16][64];
    int s = blockIdx.x;
    int tid = threadIdx.x;
    int lm = tid >> 4, lk = tid & 15;
    int ty = lm, tx = lk;

    const float* fbase = g_hf2 + (size_t)s * Bq * Hq;
    const float* rbase = g_hb2 + (size_t)(Sq - 1 - s) * Bq * Hq;

    float acc[4][4];
#pragma unroll
    for (int i = 0; i < 4; i++)
#pragma unroll
        for (int j = 0; j < 4; j++) acc[i][j] = 0.0f;

    for (int k0 = 0; k0 < KOUT; k0 += 16) {
        const float* A = (k0 < Hq) ? fbase : rbase;
        int ka = (k0 < Hq) ? k0 : (k0 - Hq);
#pragma unroll
        for (int i = 0; i < 4; i++) {
            As[lk][lm + i * 16] = A[(size_t)(lm + i * 16) * Hq + ka + lk];
            int n = lm + i * 16;
            Ws[lk][lm + i * 16] = (n < Oq) ? Wout[(size_t)n * KOUT + k0 + lk] : 0.0f;
        }
        __syncthreads();
#pragma unroll
        for (int kk = 0; kk < 16; kk++) {
            float4 av = *reinterpret_cast<const float4*>(&As[kk][ty * 4]);
            float4 wv = *reinterpret_cast<const float4*>(&Ws[kk][tx * 4]);
            float a[4] = {av.x, av.y, av.z, av.w};
            float w[4] = {wv.x, wv.y, wv.z, wv.w};
#pragma unroll
            for (int i = 0; i < 4; i++)
#pragma unroll
                for (int j = 0; j < 4; j++) acc[i][j] += a[i] * w[j];
        }
        __syncthreads();
    }

#pragma unroll
    for (int i = 0; i < 4; i++) {
        int b = ty * 4 + i;
#pragma unroll
        for (int j = 0; j < 4; j++) {
            int n = tx * 4 + j;
            if (n < Oq)
                out[((size_t)b * Sq + s) * Oq + n] = acc[i][j] + bout[n];
        }
    }
}

// ---------------- launcher ----------------------------------------------------
extern "C" void kernel_launch(void* const* d_in, const int* in_sizes, int n_in,
                              void* d_out, int out_size)
{
    const int*   src   = (const int*)  d_in[0];
    const float* emb   = (const float*)d_in[1];
    const float* Wih_f = (const float*)d_in[2];
    const float* Whh_f = (const float*)d_in[3];
    const float* b_f   = (const float*)d_in[4];
    const float* Wih_b = (const float*)d_in[5];
    const float* Whh_b = (const float*)d_in[6];
    const float* b_b   = (const float*)d_in[7];
    const float* Wout  = (const float*)d_in[8];
    const float* bout  = (const float*)d_in[9];
    float* out = (float*)d_out;

    cudaFuncSetAttribute(steps2_k,
                         cudaFuncAttributeMaxDynamicSharedMemorySize, SMEM_ST_BYTES);

    embed_k<<<Sq * Bq, 256>>>(src, emb);

    for (int l = 0; l < 2; l++) {
        pregemm_mma<<<dim3(32, 256), 256>>>(
            (l == 0) ? 0 : 1, Wih_f + (size_t)l * Gq * Eq, b_f + l * Gq, 0, 0);
        pregemm_mma<<<dim3(32, 256), 256>>>(
            (l == 0) ? 0 : 2, Wih_b + (size_t)l * Gq * Eq, b_b + l * Gq, 1,
            (l == 0) ? 1 : 0);

        whround_k<<<(2 * Gq * (Hq / 4)) / 256, 256>>>(
            Whh_f + (size_t)l * Gq * Hq, Whh_b + (size_t)l * Gq * Hq);

        steps2_k<<<128, 128, SMEM_ST_BYTES>>>(l);
    }

    outgemm_k<<<Sq, 256>>>(Wout, bout, out);
}

// round 13
// speedup vs baseline: 5.1047x; 1.0846x over previous
#include <cuda_runtime.h>
#include <cstdint>

// Problem constants
#define Bq 64
#define Sq 512
#define Eq 1024
#define Hq 1024
#define Gq 4096     // 4*H
#define Oq 50
#define KOUT 2048   // 2*H

// ---------------- scratch (device globals; no runtime allocation) ----------
__device__ float g_x  [(size_t)Sq*Bq*Eq];   // embedded input, (S,B,E)
__device__ float g_hf1[(size_t)Sq*Bq*Hq];   // fwd layer-1 output (S,B,H)
__device__ float g_hb1[(size_t)Sq*Bq*Hq];   // bwd layer-1 output (u=reversed time)
__device__ float g_hf2[(size_t)Sq*Bq*Hq];   // fwd layer-2 output
__device__ float g_hb2[(size_t)Sq*Bq*Hq];   // bwd layer-2 output (u order)
__device__ float g_gf [(size_t)Sq*Bq*Gq];   // fwd pre-gates for current layer
__device__ float g_gb [(size_t)Sq*Bq*Gq];   // bwd pre-gates for current layer
__device__ float g_wh [(size_t)2*Gq*Hq];    // tf32-rounded Whh (both dirs, current layer)

// grid-barrier state (monotonic across launches & graph replays)
__device__ volatile unsigned g_flags[128];
__device__ unsigned g_epoch = 0;

// ---------------- helpers ---------------------------------------------------
__device__ __forceinline__ float sigf(float x) {
    return __fdividef(1.0f, 1.0f + __expf(-x));
}
__device__ __forceinline__ float tanhfast(float x) {
    return __fdividef(2.0f, 1.0f + __expf(-2.0f * x)) - 1.0f;
}

// round fp32 -> tf32 (rna), keep in fp32 container
__device__ __forceinline__ float tf32r(float x) {
    uint32_t u;
    asm("cvt.rna.tf32.f32 %0, %1;" : "=r"(u) : "f"(x));
    return __uint_as_float(u);
}

__device__ __forceinline__ uint32_t smem_u32(const void* p) {
    uint32_t a;
    asm("{ .reg .u64 t; cvta.to.shared.u64 t, %1; cvt.u32.u64 %0, t; }"
        : "=r"(a) : "l"(p));
    return a;
}

// D(16x8,f32) += A(16x8,tf32,row) * B(8x8,tf32,col)
__device__ __forceinline__ void mma_tf32(float* d, const float* a, float b0f, float b1f) {
    asm volatile(
        "mma.sync.aligned.m16n8k8.row.col.f32.tf32.tf32.f32 "
        "{%0,%1,%2,%3}, {%4,%5,%6,%7}, {%8,%9}, {%0,%1,%2,%3};"
        : "+f"(d[0]), "+f"(d[1]), "+f"(d[2]), "+f"(d[3])
        : "r"(__float_as_uint(a[0])), "r"(__float_as_uint(a[1])),
          "r"(__float_as_uint(a[2])), "r"(__float_as_uint(a[3])),
          "r"(__float_as_uint(b0f)), "r"(__float_as_uint(b1f)));
}

#define CP16(dst, src) \
    asm volatile("cp.async.cg.shared.global [%0], [%1], 16;" \
                 :: "r"(dst), "l"(src) : "memory")
#define CPCOMMIT() asm volatile("cp.async.commit_group;" ::: "memory")
#define CPWAIT(n)  asm volatile("cp.async.wait_group " #n ";" ::: "memory")

// ---------------- embedding gather ------------------------------------------
__global__ void embed_k(const int* __restrict__ src, const float* __restrict__ emb) {
    int row = blockIdx.x;           // s*B + b
    int s = row >> 6;
    int b = row & 63;
    int v = src[b * Sq + s];
    const float4* e4 = reinterpret_cast<const float4*>(emb + (size_t)v * Eq);
    float4* d4 = reinterpret_cast<float4*>(g_x + (size_t)row * Eq);
    d4[threadIdx.x] = e4[threadIdx.x];
}

// ---------------- Whh tf32 pre-round (per layer) -----------------------------
__global__ void whround_k(const float* __restrict__ Wf, const float* __restrict__ Wb) {
    size_t i = (size_t)blockIdx.x * blockDim.x + threadIdx.x;   // float4 index
    const size_t NF = (size_t)Gq * Hq / 4;
    float4 v;
    float4* dst = reinterpret_cast<float4*>(g_wh);
    if (i < NF) v = reinterpret_cast<const float4*>(Wf)[i];
    else        v = reinterpret_cast<const float4*>(Wb)[i - NF];
    v.x = tf32r(v.x); v.y = tf32r(v.y); v.z = tf32r(v.z); v.w = tf32r(v.w);
    dst[i] = v;
}

// ---------------- tf32 mma.sync pre-gates GEMM -------------------------------
// gates[m][n] = sum_k in[row(m)][k] * W[n][k] + bias[n]
__global__ __launch_bounds__(256) void pregemm_mma(
    int insel, const float* __restrict__ W0, const float* __restrict__ bias,
    int dirout, int rev)
{
    __shared__ float As[128][36];
    __shared__ float Ws[128][36];
    __shared__ float s_bias[128];

    const float* in = (insel == 0) ? g_x : ((insel == 1) ? g_hf1 : g_hb1);
    float* gates = dirout ? g_gb : g_gf;

    const int n0 = blockIdx.x * 128;
    const int m0 = blockIdx.y * 128;
    const int tid = threadIdx.x;
    const int wid = tid >> 5;
    const int lane = tid & 31;
    const int warp_m = wid & 3;
    const int warp_n = wid >> 2;
    const int g = lane >> 2;
    const int c = lane & 3;

    if (tid < 128) s_bias[tid] = bias[n0 + tid];

    const int tr = tid >> 1;
    const int tc = tid & 1;
    const int m_in = m0 + tr;
    const int t_in = m_in >> 6, b_in = m_in & 63;
    const int tin = rev ? (Sq - 1 - t_in) : t_in;
    const float* aptr = in + ((size_t)tin * Bq + b_in) * Eq + tc * 16;
    const float* wptr = W0 + (size_t)(n0 + tr) * Eq + tc * 16;

    float acc[2][8][4];
#pragma unroll
    for (int mt = 0; mt < 2; mt++)
#pragma unroll
        for (int nt = 0; nt < 8; nt++)
#pragma unroll
            for (int r = 0; r < 4; r++) acc[mt][nt][r] = 0.0f;

    float4 ra[4], rw[4];
#pragma unroll
    for (int j = 0; j < 4; j++) {
        ra[j] = *reinterpret_cast<const float4*>(aptr + j * 4);
        rw[j] = *reinterpret_cast<const float4*>(wptr + j * 4);
    }

    for (int kc = 0; kc < Eq / 32; kc++) {
        __syncthreads();
#pragma unroll
        for (int j = 0; j < 4; j++) {
            float4 va, vw;
            va.x = tf32r(ra[j].x); va.y = tf32r(ra[j].y);
            va.z = tf32r(ra[j].z); va.w = tf32r(ra[j].w);
            vw.x = tf32r(rw[j].x); vw.y = tf32r(rw[j].y);
            vw.z = tf32r(rw[j].z); vw.w = tf32r(rw[j].w);
            *reinterpret_cast<float4*>(&As[tr][tc * 16 + j * 4]) = va;
            *reinterpret_cast<float4*>(&Ws[tr][tc * 16 + j * 4]) = vw;
        }
        if (kc + 1 < Eq / 32) {
            int koff = (kc + 1) * 32;
#pragma unroll
            for (int j = 0; j < 4; j++) {
                ra[j] = *reinterpret_cast<const float4*>(aptr + koff + j * 4);
                rw[j] = *reinterpret_cast<const float4*>(wptr + koff + j * 4);
            }
        }
        __syncthreads();

#pragma unroll
        for (int ks = 0; ks < 4; ks++) {
            const int kb = ks * 8;
            float a[2][4];
#pragma unroll
            for (int mt = 0; mt < 2; mt++) {
                int row = warp_m * 32 + mt * 16;
                a[mt][0] = As[row + g][kb + c];
                a[mt][1] = As[row + 8 + g][kb + c];
                a[mt][2] = As[row + g][kb + c + 4];
                a[mt][3] = As[row + 8 + g][kb + c + 4];
            }
#pragma unroll
            for (int nt = 0; nt < 8; nt++) {
                int nb = warp_n * 64 + nt * 8;
                float b0 = Ws[nb + g][kb + c];
                float b1 = Ws[nb + g][kb + c + 4];
                mma_tf32(acc[0][nt], a[0], b0, b1);
                mma_tf32(acc[1][nt], a[1], b0, b1);
            }
        }
    }

#pragma unroll
    for (int mt = 0; mt < 2; mt++) {
        int r0 = m0 + warp_m * 32 + mt * 16 + g;
#pragma unroll
        for (int nt = 0; nt < 8; nt++) {
            int col = warp_n * 64 + nt * 8 + c * 2;
            float2 v0, v1;
            v0.x = acc[mt][nt][0] + s_bias[col];
            v0.y = acc[mt][nt][1] + s_bias[col + 1];
            v1.x = acc[mt][nt][2] + s_bias[col];
            v1.y = acc[mt][nt][3] + s_bias[col + 1];
            *reinterpret_cast<float2*>(&gates[(size_t)r0 * Gq + n0 + col]) = v0;
            *reinterpret_cast<float2*>(&gates[(size_t)(r0 + 8) * Gq + n0 + col]) = v1;
        }
    }
}

// ---------------- persistent tensor-core recurrence (v3) ---------------------
// 128 CTAs (cta = d*64 + q), 256 threads / 8 warps.
// Warp grid: warp_m(2) x warp_n(2) x kg(2 K-split groups). Warp tile 32x32.
// K chunks of 128, cp.async double-buffered; kg partials in two sg buffers,
// summed during activation. Whh tf32-pre-rounded in g_wh; h stored tf32-rounded.
#define ST3 132                 // padded row stride (floats) for 128-wide chunk
#define ABUF3 (64 * ST3)        // 8448 floats per tile
#define STAGE3 (2 * ABUF3)      // A + B per stage
#define SG3_OFF (2 * STAGE3)    // two stages
#define PRE3_OFF (SG3_OFF + 2 * 64 * 65)
#define CS3_OFF  (PRE3_OFF + 64 * 64)
#define HS3_OFF  (CS3_OFF + 16 * 65)
#define SMEM3_FLOATS (HS3_OFF + 64 * 16)
#define SMEM3_BYTES  (SMEM3_FLOATS * 4)

__global__ __launch_bounds__(256) void steps3_k(int l)
{
    extern __shared__ float smf[];
    float* sg    = smf + SG3_OFF;      // 2 x (64x65)
    float* pre_s = smf + PRE3_OFF;     // 64x64
    float* c_s   = smf + CS3_OFF;      // 16x65
    float* h_s   = smf + HS3_OFF;      // 64x16

    const int cta = blockIdx.x;
    const int d = cta >> 6;
    const int q = cta & 63;
    const float* pre = d ? g_gb : g_gf;
    const float* whb = g_wh + (size_t)d * Gq * Hq;
    float* hseq = l ? (d ? g_hb2 : g_hf2) : (d ? g_hb1 : g_hf1);

    const int tid = threadIdx.x;
    const int wid = tid >> 5;
    const int lane = tid & 31;
    const int warp_m = wid & 1;
    const int warp_n = (wid >> 1) & 1;
    const int kg = wid >> 2;
    const int g_ = lane >> 2;
    const int c_ = lane & 3;

    const uint32_t sbase = smem_u32(smf);

    // cp.async mapping: float4 index f = tid + j*256 -> row = (tid>>5)+8j, col4 = tid&31
    const int lr0 = tid >> 5;
    const int lc4 = tid & 31;
    const float* wrow[8];
#pragma unroll
    for (int j = 0; j < 8; j++) {
        int r = lr0 + 8 * j;
        int gr = (r >> 4) * 1024 + q * 16 + (r & 15);
        wrow[j] = whb + (size_t)gr * Hq + lc4 * 4;
    }

    const unsigned e = g_epoch;

    for (int i = tid; i < 16 * 65; i += 256) c_s[i] = 0.0f;
    __syncthreads();

    const int u = tid & 15;          // local unit
    const int bg = tid >> 4;         // batch group (4 batches)

    for (int t = 0; t < Sq; t++) {
        // stage pre-gates (1 cp.async group): 1024 float4s over 256 threads
#pragma unroll
        for (int j = 0; j < 4; j++) {
            int idx = tid + j * 256;
            int b = idx >> 4, rem = idx & 15;
            int gg = rem >> 2, qt = rem & 3;
            const float* src = pre + ((size_t)t * Bq + b) * Gq + gg * 1024 + q * 16 + qt * 4;
            uint32_t dst = sbase + (uint32_t)((PRE3_OFF + b * 64 + gg * 16 + qt * 4) * 4);
            CP16(dst, src);
        }
        CPCOMMIT();

        float acc[2][4][4];
#pragma unroll
        for (int mt = 0; mt < 2; mt++)
#pragma unroll
            for (int nt = 0; nt < 4; nt++)
#pragma unroll
                for (int r = 0; r < 4; r++) acc[mt][nt][r] = 0.0f;

        if (t > 0) {
            const float* hprev = hseq + (size_t)(t - 1) * Bq * Hq;
            auto issue = [&](int ic) {
                int k0 = ic * 128;
                uint32_t ab = sbase + (uint32_t)(((ic & 1) * STAGE3) * 4);
                uint32_t bb = ab + (uint32_t)(ABUF3 * 4);
#pragma unroll
                for (int j = 0; j < 8; j++) {
                    int r = lr0 + 8 * j;
                    uint32_t soff = (uint32_t)((r * ST3 + lc4 * 4) * 4);
                    CP16(ab + soff, hprev + (size_t)r * Hq + k0 + lc4 * 4);
                    CP16(bb + soff, wrow[j] + k0);
                }
            };
            issue(0); CPCOMMIT();
            issue(1); CPCOMMIT();
            for (int ic = 0; ic < 8; ic++) {
                if (ic < 7) { CPWAIT(1); } else { CPWAIT(0); }
                __syncthreads();
                const float* Asm = smf + (ic & 1) * STAGE3;
                const float* Bsm = Asm + ABUF3;
#pragma unroll
                for (int ks = 0; ks < 8; ks++) {
                    const int kb = kg * 64 + ks * 8;
                    float a[2][4];
#pragma unroll
                    for (int mt = 0; mt < 2; mt++) {
                        int rr = warp_m * 32 + mt * 16;
                        a[mt][0] = Asm[(rr + g_) * ST3 + kb + c_];
                        a[mt][1] = Asm[(rr + 8 + g_) * ST3 + kb + c_];
                        a[mt][2] = Asm[(rr + g_) * ST3 + kb + c_ + 4];
                        a[mt][3] = Asm[(rr + 8 + g_) * ST3 + kb + c_ + 4];
                    }
#pragma unroll
                    for (int nt = 0; nt < 4; nt++) {
                        int nb = warp_n * 32 + nt * 8;
                        float b0 = Bsm[(nb + g_) * ST3 + kb + c_];
                        float b1 = Bsm[(nb + g_) * ST3 + kb + c_ + 4];
                        mma_tf32(acc[0][nt], a[0], b0, b1);
                        mma_tf32(acc[1][nt], a[1], b0, b1);
                    }
                }
                __syncthreads();
                if (ic + 2 < 8) { issue(ic + 2); CPCOMMIT(); }
            }
        } else {
            CPWAIT(0);
            __syncthreads();
        }

        // acc -> sg[kg][n_local][batch]
        float* sgk = sg + kg * (64 * 65);
#pragma unroll
        for (int mt = 0; mt < 2; mt++) {
            int ml = warp_m * 32 + mt * 16 + g_;
#pragma unroll
            for (int nt = 0; nt < 4; nt++) {
                int nl = warp_n * 32 + nt * 8 + c_ * 2;
                sgk[nl * 65 + ml]           = acc[mt][nt][0];
                sgk[(nl + 1) * 65 + ml]     = acc[mt][nt][1];
                sgk[nl * 65 + ml + 8]       = acc[mt][nt][2];
                sgk[(nl + 1) * 65 + ml + 8] = acc[mt][nt][3];
            }
        }
        __syncthreads();

        // activations: thread = (unit u, batch group bg), 4 batches
#pragma unroll
        for (int j = 0; j < 4; j++) {
            int b = bg * 4 + j;
            float gi = sg[u * 65 + b]        + sg[64*65 + u * 65 + b]        + pre_s[b * 64 + u];
            float gf = sg[(16 + u) * 65 + b] + sg[64*65 + (16 + u) * 65 + b] + pre_s[b * 64 + 16 + u];
            float gg = sg[(32 + u) * 65 + b] + sg[64*65 + (32 + u) * 65 + b] + pre_s[b * 64 + 32 + u];
            float go = sg[(48 + u) * 65 + b] + sg[64*65 + (48 + u) * 65 + b] + pre_s[b * 64 + 48 + u];
            float cold = c_s[u * 65 + b];
            float cnew = sigf(gf) * cold + sigf(gi) * tanhfast(gg);
            c_s[u * 65 + b] = cnew;
            h_s[b * 16 + u] = tf32r(sigf(go) * tanhfast(cnew));
        }
        __syncthreads();

        // coalesced STG of h(t): 256 threads, one float4 each
        {
            int b = tid >> 2, qt = tid & 3;
            float4 v = *reinterpret_cast<const float4*>(&h_s[b * 16 + qt * 4]);
            *reinterpret_cast<float4*>(
                &hseq[((size_t)t * Bq + b) * Hq + q * 16 + qt * 4]) = v;
        }

        // per-direction grid barrier (release h(t))
        __syncthreads();
        __threadfence();
        if (tid == 0) g_flags[cta] = e + t + 1;
        if (tid < 64) {
            unsigned tgt = e + t + 1;
            while (g_flags[d * 64 + tid] < tgt) __nanosleep(64);
        }
        __syncthreads();
    }

    if (cta == 0 && tid == 0) g_epoch = e + Sq;
}

// ---------------- output GEMM: out = concat(f, r_rev) @ Wout^T + bout --------
__global__ __launch_bounds__(256) void outgemm_k(
    const float* __restrict__ Wout, const float* __restrict__ bout,
    float* __restrict__ out)
{
    __shared__ float As[16][64];
    __shared__ float Ws[16][64];
    int s = blockIdx.x;
    int tid = threadIdx.x;
    int lm = tid >> 4, lk = tid & 15;
    int ty = lm, tx = lk;

    const float* fbase = g_hf2 + (size_t)s * Bq * Hq;
    const float* rbase = g_hb2 + (size_t)(Sq - 1 - s) * Bq * Hq;

    float acc[4][4];
#pragma unroll
    for (int i = 0; i < 4; i++)
#pragma unroll
        for (int j = 0; j < 4; j++) acc[i][j] = 0.0f;

    for (int k0 = 0; k0 < KOUT; k0 += 16) {
        const float* A = (k0 < Hq) ? fbase : rbase;
        int ka = (k0 < Hq) ? k0 : (k0 - Hq);
#pragma unroll
        for (int i = 0; i < 4; i++) {
            As[lk][lm + i * 16] = A[(size_t)(lm + i * 16) * Hq + ka + lk];
            int n = lm + i * 16;
            Ws[lk][lm + i * 16] = (n < Oq) ? Wout[(size_t)n * KOUT + k0 + lk] : 0.0f;
        }
        __syncthreads();
#pragma unroll
        for (int kk = 0; kk < 16; kk++) {
            float4 av = *reinterpret_cast<const float4*>(&As[kk][ty * 4]);
            float4 wv = *reinterpret_cast<const float4*>(&Ws[kk][tx * 4]);
            float a[4] = {av.x, av.y, av.z, av.w};
            float w[4] = {wv.x, wv.y, wv.z, wv.w};
#pragma unroll
            for (int i = 0; i < 4; i++)
#pragma unroll
                for (int j = 0; j < 4; j++) acc[i][j] += a[i] * w[j];
        }
        __syncthreads();
    }

#pragma unroll
    for (int i = 0; i < 4; i++) {
        int b = ty * 4 + i;
#pragma unroll
        for (int j = 0; j < 4; j++) {
            int n = tx * 4 + j;
            if (n < Oq)
                out[((size_t)b * Sq + s) * Oq + n] = acc[i][j] + bout[n];
        }
    }
}

// ---------------- launcher ----------------------------------------------------
extern "C" void kernel_launch(void* const* d_in, const int* in_sizes, int n_in,
                              void* d_out, int out_size)
{
    const int*   src   = (const int*)  d_in[0];
    const float* emb   = (const float*)d_in[1];
    const float* Wih_f = (const float*)d_in[2];
    const float* Whh_f = (const float*)d_in[3];
    const float* b_f   = (const float*)d_in[4];
    const float* Wih_b = (const float*)d_in[5];
    const float* Whh_b = (const float*)d_in[6];
    const float* b_b   = (const float*)d_in[7];
    const float* Wout  = (const float*)d_in[8];
    const float* bout  = (const float*)d_in[9];
    float* out = (float*)d_out;

    cudaFuncSetAttribute(steps3_k,
                         cudaFuncAttributeMaxDynamicSharedMemorySize, SMEM3_BYTES);

    embed_k<<<Sq * Bq, 256>>>(src, emb);

    for (int l = 0; l < 2; l++) {
        pregemm_mma<<<dim3(32, 256), 256>>>(
            (l == 0) ? 0 : 1, Wih_f + (size_t)l * Gq * Eq, b_f + l * Gq, 0, 0);
        pregemm_mma<<<dim3(32, 256), 256>>>(
            (l == 0) ? 0 : 2, Wih_b + (size_t)l * Gq * Eq, b_b + l * Gq, 1,
            (l == 0) ? 1 : 0);

        whround_k<<<(2 * Gq * (Hq / 4)) / 256, 256>>>(
            Whh_f + (size_t)l * Gq * Hq, Whh_b + (size_t)l * Gq * Hq);

        steps3_k<<<128, 256, SMEM3_BYTES>>>(l);
    }

    outgemm_k<<<Sq, 256>>>(Wout, bout, out);
}

// round 15
// speedup vs baseline: 7.1527x; 1.4012x over previous
#include <cuda_runtime.h>
#include <cuda_fp16.h>
#include <cstdint>

// Problem constants
#define Bq 64
#define Sq 512
#define Eq 1024
#define Hq 1024
#define Gq 4096     // 4*H
#define Oq 50
#define KOUT 2048   // 2*H

// ---------------- scratch (device globals; no runtime allocation) ----------
__device__ __half g_x16 [(size_t)Sq*Bq*Eq];     // embedded input, fp16
__device__ __half g_h16 [4][(size_t)Sq*Bq*Hq];  // h seqs: f1,b1,f2,b2 (fp16)
__device__ float  g_gf  [(size_t)Sq*Bq*Gq];     // fwd pre-gates (fp32)
__device__ float  g_gb  [(size_t)Sq*Bq*Gq];     // bwd pre-gates (fp32)
__device__ __half g_wh16[(size_t)2*Gq*Hq];      // fp16 Whh (both dirs, cur layer)

// grid-barrier state (monotonic across launches & graph replays)
__device__ volatile unsigned g_flags[128];
__device__ unsigned g_epoch = 0;

// ---------------- helpers ---------------------------------------------------
__device__ __forceinline__ float sigf(float x) {
    return __fdividef(1.0f, 1.0f + __expf(-x));
}
__device__ __forceinline__ float tanhfast(float x) {
    return __fdividef(2.0f, 1.0f + __expf(-2.0f * x)) - 1.0f;
}
__device__ __forceinline__ uint32_t smem_u32(const void* p) {
    uint32_t a;
    asm("{ .reg .u64 t; cvta.to.shared.u64 t, %1; cvt.u32.u64 %0, t; }"
        : "=r"(a) : "l"(p));
    return a;
}
__device__ __forceinline__ uint32_t packh2(float a, float b) {
    __half2 h = __floats2half2_rn(a, b);          // .x=a (lo), .y=b (hi)
    return *reinterpret_cast<uint32_t*>(&h);
}

// D(16x8,f32) += A(16x16,f16,row) * B(16x8,f16,col)
__device__ __forceinline__ void mma_f16(float* d, const uint32_t* a,
                                        uint32_t b0, uint32_t b1) {
    asm volatile(
        "mma.sync.aligned.m16n8k16.row.col.f32.f16.f16.f32 "
        "{%0,%1,%2,%3}, {%4,%5,%6,%7}, {%8,%9}, {%0,%1,%2,%3};"
        : "+f"(d[0]), "+f"(d[1]), "+f"(d[2]), "+f"(d[3])
        : "r"(a[0]), "r"(a[1]), "r"(a[2]), "r"(a[3]), "r"(b0), "r"(b1));
}

#define CP16(dst, src) \
    asm volatile("cp.async.cg.shared.global [%0], [%1], 16;" \
                 :: "r"(dst), "l"(src) : "memory")
#define CPCOMMIT() asm volatile("cp.async.commit_group;" ::: "memory")
#define CPWAIT(n)  asm volatile("cp.async.wait_group " #n ";" ::: "memory")

// ---------------- embedding gather (fp32 emb -> fp16 x) ----------------------
__global__ void embed16_k(const int* __restrict__ src, const float* __restrict__ emb) {
    int row = blockIdx.x;           // s*B + b
    int s = row >> 6;
    int b = row & 63;
    int v = src[b * Sq + s];
    float4 f = reinterpret_cast<const float4*>(emb + (size_t)v * Eq)[threadIdx.x];
    uint2 u;
    u.x = packh2(f.x, f.y);
    u.y = packh2(f.z, f.w);
    *reinterpret_cast<uint2*>(g_x16 + (size_t)row * Eq + threadIdx.x * 4) = u;
}

// ---------------- Whh fp32 -> fp16 (per layer, both directions) --------------
__global__ void whconv16_k(const float* __restrict__ Wf, const float* __restrict__ Wb) {
    size_t i = (size_t)blockIdx.x * blockDim.x + threadIdx.x;   // float4 index
    const size_t NF = (size_t)Gq * Hq / 4;
    float4 v = (i < NF) ? reinterpret_cast<const float4*>(Wf)[i]
                        : reinterpret_cast<const float4*>(Wb)[i - NF];
    uint2 u;
    u.x = packh2(v.x, v.y);
    u.y = packh2(v.z, v.w);
    reinterpret_cast<uint2*>(g_wh16)[i] = u;
}

// ---------------- fp16 mma.sync pre-gates GEMM -------------------------------
// gates[m][n] = sum_k in16[row(m)][k] * W[n][k] + bias[n]   (fp32 out)
// CTA 128x128, 8 warps 4(M)x2(N), warp tile 32x64, mma m16n8k16 f16.
// grid: (Gq/128=32, 32768/128=256), 256 threads.
#define PST 20   // half2 row stride in smem chunk (16 data + 4 pad)
__global__ __launch_bounds__(256) void pregemm16(
    int insel, const float* __restrict__ W0, const float* __restrict__ bias,
    int dirout, int rev)
{
    __shared__ uint32_t As2[128 * PST];
    __shared__ uint32_t Ws2[128 * PST];
    __shared__ float s_bias[128];

    const __half* in16 = (insel == 0) ? g_x16 : ((insel == 1) ? g_h16[0] : g_h16[1]);
    float* gates = dirout ? g_gb : g_gf;

    const int n0 = blockIdx.x * 128;
    const int m0 = blockIdx.y * 128;
    const int tid = threadIdx.x;
    const int wid = tid >> 5;
    const int lane = tid & 31;
    const int warp_m = wid & 3;
    const int warp_n = wid >> 2;
    const int g = lane >> 2;
    const int c = lane & 3;

    if (tid < 128) s_bias[tid] = bias[n0 + tid];

    const int tr = tid >> 1;
    const int tc = tid & 1;
    const int m_in = m0 + tr;
    const int t_in = m_in >> 6, b_in = m_in & 63;
    const int tin = rev ? (Sq - 1 - t_in) : t_in;
    const __half* aptr = in16 + ((size_t)tin * Bq + b_in) * Eq + tc * 16;
    const float*  wptr = W0 + (size_t)(n0 + tr) * Eq + tc * 16;

    float acc[2][8][4];
#pragma unroll
    for (int mt = 0; mt < 2; mt++)
#pragma unroll
        for (int nt = 0; nt < 8; nt++)
#pragma unroll
            for (int r = 0; r < 4; r++) acc[mt][nt][r] = 0.0f;

    uint4 rau[2];
    float4 rwf[4];
    rau[0] = *reinterpret_cast<const uint4*>(aptr);
    rau[1] = *reinterpret_cast<const uint4*>(aptr + 8);
#pragma unroll
    for (int j = 0; j < 4; j++) rwf[j] = *reinterpret_cast<const float4*>(wptr + j * 4);

    for (int kc = 0; kc < Eq / 32; kc++) {
        __syncthreads();
        // STS A (already fp16)
        *reinterpret_cast<uint4*>(&As2[tr * PST + tc * 8])     = rau[0];
        *reinterpret_cast<uint4*>(&As2[tr * PST + tc * 8 + 4]) = rau[1];
        // STS W (cvt fp32->fp16x2)
        {
            uint4 w0, w1;
            w0.x = packh2(rwf[0].x, rwf[0].y); w0.y = packh2(rwf[0].z, rwf[0].w);
            w0.z = packh2(rwf[1].x, rwf[1].y); w0.w = packh2(rwf[1].z, rwf[1].w);
            w1.x = packh2(rwf[2].x, rwf[2].y); w1.y = packh2(rwf[2].z, rwf[2].w);
            w1.z = packh2(rwf[3].x, rwf[3].y); w1.w = packh2(rwf[3].z, rwf[3].w);
            *reinterpret_cast<uint4*>(&Ws2[tr * PST + tc * 8])     = w0;
            *reinterpret_cast<uint4*>(&Ws2[tr * PST + tc * 8 + 4]) = w1;
        }
        if (kc + 1 < Eq / 32) {
            int koff = (kc + 1) * 32;
            rau[0] = *reinterpret_cast<const uint4*>(aptr + koff);
            rau[1] = *reinterpret_cast<const uint4*>(aptr + koff + 8);
#pragma unroll
            for (int j = 0; j < 4; j++)
                rwf[j] = *reinterpret_cast<const float4*>(wptr + koff + j * 4);
        }
        __syncthreads();

#pragma unroll
        for (int ks = 0; ks < 2; ks++) {
            const int kb = ks * 8;
            uint32_t a[2][4];
#pragma unroll
            for (int mt = 0; mt < 2; mt++) {
                int row = warp_m * 32 + mt * 16;
                a[mt][0] = As2[(row + g) * PST + kb + c];
                a[mt][1] = As2[(row + 8 + g) * PST + kb + c];
                a[mt][2] = As2[(row + g) * PST + kb + c + 4];
                a[mt][3] = As2[(row + 8 + g) * PST + kb + c + 4];
            }
#pragma unroll
            for (int nt = 0; nt < 8; nt++) {
                int nb = warp_n * 64 + nt * 8;
                uint32_t b0 = Ws2[(nb + g) * PST + kb + c];
                uint32_t b1 = Ws2[(nb + g) * PST + kb + c + 4];
                mma_f16(acc[0][nt], a[0], b0, b1);
                mma_f16(acc[1][nt], a[1], b0, b1);
            }
        }
    }

#pragma unroll
    for (int mt = 0; mt < 2; mt++) {
        int r0 = m0 + warp_m * 32 + mt * 16 + g;
#pragma unroll
        for (int nt = 0; nt < 8; nt++) {
            int col = warp_n * 64 + nt * 8 + c * 2;
            float2 v0, v1;
            v0.x = acc[mt][nt][0] + s_bias[col];
            v0.y = acc[mt][nt][1] + s_bias[col + 1];
            v1.x = acc[mt][nt][2] + s_bias[col];
            v1.y = acc[mt][nt][3] + s_bias[col + 1];
            *reinterpret_cast<float2*>(&gates[(size_t)r0 * Gq + n0 + col]) = v0;
            *reinterpret_cast<float2*>(&gates[(size_t)(r0 + 8) * Gq + n0 + col]) = v1;
        }
    }
}

// ---------------- persistent fp16 tensor-core recurrence ---------------------
// 128 CTAs (cta = d*64 + q), 256 threads / 8 warps: warp_m(2) x warp_n(2) x kg(2).
// K chunks of 256 halves, cp.async double-buffered. h kept fp16 end-to-end.
#define ST4 132                         // half2 per smem tile row (128 + 4 pad)
#define ABUF4 (64 * ST4)                // half2 per tile
#define STAGE4 (2 * ABUF4)              // A + B per stage (half2)
#define SG4_OFF   (2 * STAGE4 * 4)      // bytes: 2 stages of half2(4B)
#define PRE4_OFF  (SG4_OFF + 2 * 64 * 65 * 4)
#define CS4_OFF   (PRE4_OFF + 64 * 64 * 4)
#define HS4_OFF   (CS4_OFF + 16 * 65 * 4)
#define SMEM4_BYTES (HS4_OFF + 64 * 16 * 2)

__global__ __launch_bounds__(256) void steps4_k(int l)
{
    extern __shared__ char smc[];
    float*  sg    = reinterpret_cast<float*>(smc + SG4_OFF);    // 2 x (64x65)
    float*  pre_s = reinterpret_cast<float*>(smc + PRE4_OFF);   // 64x64
    float*  c_s   = reinterpret_cast<float*>(smc + CS4_OFF);    // 16x65
    __half* h16_s = reinterpret_cast<__half*>(smc + HS4_OFF);   // 64x16

    const int cta = blockIdx.x;
    const int d = cta >> 6;
    const int q = cta & 63;
    const float*  pre = d ? g_gb : g_gf;
    const __half* whb = g_wh16 + (size_t)d * Gq * Hq;
    __half* hseq = g_h16[l * 2 + d];

    const int tid = threadIdx.x;
    const int wid = tid >> 5;
    const int lane = tid & 31;
    const int warp_m = wid & 1;
    const int warp_n = (wid >> 1) & 1;
    const int kg = wid >> 2;
    const int g_ = lane >> 2;
    const int c_ = lane & 3;

    const uint32_t sbase = smem_u32(smc);

    // cp.async mapping: f = tid + j*256 -> row = f>>5 (0..63), c16 = f&31
    const int lr0 = tid >> 5;
    const int c16 = tid & 31;
    const __half* wrow[8];
#pragma unroll
    for (int j = 0; j < 8; j++) {
        int r = lr0 + 8 * j;
        int gr = (r >> 4) * 1024 + q * 16 + (r & 15);
        wrow[j] = whb + (size_t)gr * Hq + c16 * 8;
    }

    const unsigned e = g_epoch;

    for (int i = tid; i < 16 * 65; i += 256) c_s[i] = 0.0f;
    __syncthreads();

    const int u = tid & 15;          // local unit
    const int bg = tid >> 4;         // batch group (4 batches)

    for (int t = 0; t < Sq; t++) {
        // stage pre-gates (fp32, own group): 1024 x 16B over 256 threads
#pragma unroll
        for (int j = 0; j < 4; j++) {
            int idx = tid + j * 256;
            int b = idx >> 4, rem = idx & 15;
            int gg = rem >> 2, qt = rem & 3;
            const float* src = pre + ((size_t)t * Bq + b) * Gq + gg * 1024 + q * 16 + qt * 4;
            uint32_t dst = sbase + (uint32_t)(PRE4_OFF + (b * 64 + gg * 16 + qt * 4) * 4);
            CP16(dst, src);
        }
        CPCOMMIT();

        float acc[2][4][4];
#pragma unroll
        for (int mt = 0; mt < 2; mt++)
#pragma unroll
            for (int nt = 0; nt < 4; nt++)
#pragma unroll
                for (int r = 0; r < 4; r++) acc[mt][nt][r] = 0.0f;

        if (t > 0) {
            const __half* hprev = hseq + (size_t)(t - 1) * Bq * Hq;
            auto issue = [&](int ic) {
                int k0 = ic * 256;                          // halves
                uint32_t ab = sbase + (uint32_t)((ic & 1) * STAGE4 * 4);
                uint32_t bb = ab + (uint32_t)(ABUF4 * 4);
#pragma unroll
                for (int j = 0; j < 8; j++) {
                    int r = lr0 + 8 * j;
                    uint32_t soff = (uint32_t)(r * (ST4 * 4) + c16 * 16);
                    CP16(ab + soff, hprev + (size_t)r * Hq + k0 + c16 * 8);
                    CP16(bb + soff, wrow[j] + k0);
                }
            };
            issue(0); CPCOMMIT();
            issue(1); CPCOMMIT();
            for (int ic = 0; ic < 4; ic++) {
                if (ic < 3) { CPWAIT(1); } else { CPWAIT(0); }
                __syncthreads();
                const uint32_t* Asm = reinterpret_cast<const uint32_t*>(
                    smc + (size_t)(ic & 1) * STAGE4 * 4);
                const uint32_t* Bsm = Asm + ABUF4;
#pragma unroll
                for (int ks = 0; ks < 8; ks++) {
                    const int kb = kg * 64 + ks * 8;        // half2 col
                    uint32_t a[2][4];
#pragma unroll
                    for (int mt = 0; mt < 2; mt++) {
                        int rr = warp_m * 32 + mt * 16;
                        a[mt][0] = Asm[(rr + g_) * ST4 + kb + c_];
                        a[mt][1] = Asm[(rr + 8 + g_) * ST4 + kb + c_];
                        a[mt][2] = Asm[(rr + g_) * ST4 + kb + c_ + 4];
                        a[mt][3] = Asm[(rr + 8 + g_) * ST4 + kb + c_ + 4];
                    }
#pragma unroll
                    for (int nt = 0; nt < 4; nt++) {
                        int nb = warp_n * 32 + nt * 8;
                        uint32_t b0 = Bsm[(nb + g_) * ST4 + kb + c_];
                        uint32_t b1 = Bsm[(nb + g_) * ST4 + kb + c_ + 4];
                        mma_f16(acc[0][nt], a[0], b0, b1);
                        mma_f16(acc[1][nt], a[1], b0, b1);
                    }
                }
                __syncthreads();
                if (ic + 2 < 4) { issue(ic + 2); CPCOMMIT(); }
            }
        } else {
            CPWAIT(0);
            __syncthreads();
        }

        // acc -> sg[kg][n_local][batch]
        float* sgk = sg + kg * (64 * 65);
#pragma unroll
        for (int mt = 0; mt < 2; mt++) {
            int ml = warp_m * 32 + mt * 16 + g_;
#pragma unroll
            for (int nt = 0; nt < 4; nt++) {
                int nl = warp_n * 32 + nt * 8 + c_ * 2;
                sgk[nl * 65 + ml]           = acc[mt][nt][0];
                sgk[(nl + 1) * 65 + ml]     = acc[mt][nt][1];
                sgk[nl * 65 + ml + 8]       = acc[mt][nt][2];
                sgk[(nl + 1) * 65 + ml + 8] = acc[mt][nt][3];
            }
        }
        __syncthreads();

        // activations: thread = (unit u, batch group bg), 4 batches
#pragma unroll
        for (int j = 0; j < 4; j++) {
            int b = bg * 4 + j;
            float gi = sg[u * 65 + b]        + sg[64*65 + u * 65 + b]        + pre_s[b * 64 + u];
            float gf = sg[(16 + u) * 65 + b] + sg[64*65 + (16 + u) * 65 + b] + pre_s[b * 64 + 16 + u];
            float gg = sg[(32 + u) * 65 + b] + sg[64*65 + (32 + u) * 65 + b] + pre_s[b * 64 + 32 + u];
            float go = sg[(48 + u) * 65 + b] + sg[64*65 + (48 + u) * 65 + b] + pre_s[b * 64 + 48 + u];
            float cold = c_s[u * 65 + b];
            float cnew = sigf(gf) * cold + sigf(gi) * tanhfast(gg);
            c_s[u * 65 + b] = cnew;
            h16_s[b * 16 + u] = __float2half_rn(sigf(go) * tanhfast(cnew));
        }
        __syncthreads();

        // coalesced STG of h16(t): 128 threads x 16B = 2KB
        if (tid < 128) {
            int b = tid >> 1, hp = tid & 1;
            uint4 v = *reinterpret_cast<const uint4*>(h16_s + b * 16 + hp * 8);
            *reinterpret_cast<uint4*>(
                &hseq[((size_t)t * Bq + b) * Hq + q * 16 + hp * 8]) = v;
        }

        // per-direction grid barrier (release h(t))
        __syncthreads();
        __threadfence();
        if (tid == 0) g_flags[cta] = e + t + 1;
        if (tid < 64) {
            unsigned tgt = e + t + 1;
            while (g_flags[d * 64 + tid] < tgt) __nanosleep(64);
        }
        __syncthreads();
    }

    if (cta == 0 && tid == 0) g_epoch = e + Sq;
}

// ---------------- output GEMM: out = concat(f, r_rev) @ Wout^T + bout --------
__global__ __launch_bounds__(256) void outgemm16(
    const float* __restrict__ Wout, const float* __restrict__ bout,
    float* __restrict__ out)
{
    __shared__ float As[16][64];
    __shared__ float Ws[16][64];
    int s = blockIdx.x;
    int tid = threadIdx.x;
    int lm = tid >> 4, lk = tid & 15;
    int ty = lm, tx = lk;

    const __half* fbase = g_h16[2] + (size_t)s * Bq * Hq;
    const __half* rbase = g_h16[3] + (size_t)(Sq - 1 - s) * Bq * Hq;

    float acc[4][4];
#pragma unroll
    for (int i = 0; i < 4; i++)
#pragma unroll
        for (int j = 0; j < 4; j++) acc[i][j] = 0.0f;

    for (int k0 = 0; k0 < KOUT; k0 += 16) {
        const __half* A = (k0 < Hq) ? fbase : rbase;
        int ka = (k0 < Hq) ? k0 : (k0 - Hq);
#pragma unroll
        for (int i = 0; i < 4; i++) {
            As[lk][lm + i * 16] = __half2float(A[(size_t)(lm + i * 16) * Hq + ka + lk]);
            int n = lm + i * 16;
            Ws[lk][lm + i * 16] = (n < Oq) ? Wout[(size_t)n * KOUT + k0 + lk] : 0.0f;
        }
        __syncthreads();
#pragma unroll
        for (int kk = 0; kk < 16; kk++) {
            float4 av = *reinterpret_cast<const float4*>(&As[kk][ty * 4]);
            float4 wv = *reinterpret_cast<const float4*>(&Ws[kk][tx * 4]);
            float a[4] = {av.x, av.y, av.z, av.w};
            float w[4] = {wv.x, wv.y, wv.z, wv.w};
#pragma unroll
            for (int i = 0; i < 4; i++)
#pragma unroll
                for (int j = 0; j < 4; j++) acc[i][j] += a[i] * w[j];
        }
        __syncthreads();
    }

#pragma unroll
    for (int i = 0; i < 4; i++) {
        int b = ty * 4 + i;
#pragma unroll
        for (int j = 0; j < 4; j++) {
            int n = tx * 4 + j;
            if (n < Oq)
                out[((size_t)b * Sq + s) * Oq + n] = acc[i][j] + bout[n];
        }
    }
}

// ---------------- launcher ----------------------------------------------------
extern "C" void kernel_launch(void* const* d_in, const int* in_sizes, int n_in,
                              void* d_out, int out_size)
{
    const int*   src   = (const int*)  d_in[0];
    const float* emb   = (const float*)d_in[1];
    const float* Wih_f = (const float*)d_in[2];
    const float* Whh_f = (const float*)d_in[3];
    const float* b_f   = (const float*)d_in[4];
    const float* Wih_b = (const float*)d_in[5];
    const float* Whh_b = (const float*)d_in[6];
    const float* b_b   = (const float*)d_in[7];
    const float* Wout  = (const float*)d_in[8];
    const float* bout  = (const float*)d_in[9];
    float* out = (float*)d_out;

    cudaFuncSetAttribute(steps4_k,
                         cudaFuncAttributeMaxDynamicSharedMemorySize, SMEM4_BYTES);

    embed16_k<<<Sq * Bq, 256>>>(src, emb);

    for (int l = 0; l < 2; l++) {
        pregemm16<<<dim3(32, 256), 256>>>(
            (l == 0) ? 0 : 1, Wih_f + (size_t)l * Gq * Eq, b_f + l * Gq, 0, 0);
        pregemm16<<<dim3(32, 256), 256>>>(
            (l == 0) ? 0 : 2, Wih_b + (size_t)l * Gq * Eq, b_b + l * Gq, 1,
            (l == 0) ? 1 : 0);

        whconv16_k<<<(2 * Gq * (Hq / 4)) / 256, 256>>>(
            Whh_f + (size_t)l * Gq * Hq, Whh_b + (size_t)l * Gq * Hq);

        steps4_k<<<128, 256, SMEM4_BYTES>>>(l);
    }

    outgemm16<<<Sq, 256>>>(Wout, bout, out);
}

// round 17
// speedup vs baseline: 7.3851x; 1.0325x over previous
#include <cuda_runtime.h>
#include <cuda_fp16.h>
#include <cstdint>

// Problem constants
#define Bq 64
#define Sq 512
#define Eq 1024
#define Hq 1024
#define Gq 4096     // 4*H
#define Oq 50
#define KOUT 2048   // 2*H

// ---------------- scratch (device globals; no runtime allocation) ----------
__device__ __half g_x16 [(size_t)Sq*Bq*Eq];     // embedded input, fp16
__device__ __half g_h16 [4][(size_t)Sq*Bq*Hq];  // h seqs: f1,b1,f2,b2 (fp16)
__device__ float  g_gf  [(size_t)Sq*Bq*Gq];     // fwd pre-gates (fp32)
__device__ float  g_gb  [(size_t)Sq*Bq*Gq];     // bwd pre-gates (fp32)
__device__ __half g_wh16[(size_t)2*Gq*Hq];      // fp16 Whh (both dirs, cur layer)

// grid-barrier state (monotonic across launches & graph replays)
__device__ volatile unsigned g_flags[128];
__device__ unsigned g_epoch = 0;

// ---------------- helpers ---------------------------------------------------
__device__ __forceinline__ float sigf(float x) {
    return __fdividef(1.0f, 1.0f + __expf(-x));
}
__device__ __forceinline__ float tanhfast(float x) {
    return __fdividef(2.0f, 1.0f + __expf(-2.0f * x)) - 1.0f;
}
__device__ __forceinline__ uint32_t smem_u32(const void* p) {
    uint32_t a;
    asm("{ .reg .u64 t; cvta.to.shared.u64 t, %1; cvt.u32.u64 %0, t; }"
        : "=r"(a) : "l"(p));
    return a;
}
__device__ __forceinline__ uint32_t packh2(float a, float b) {
    __half2 h = __floats2half2_rn(a, b);
    return *reinterpret_cast<uint32_t*>(&h);
}

// D(16x8,f32) += A(16x16,f16,row) * B(16x8,f16,col)
__device__ __forceinline__ void mma_f16(float* d, const uint32_t* a,
                                        uint32_t b0, uint32_t b1) {
    asm volatile(
        "mma.sync.aligned.m16n8k16.row.col.f32.f16.f16.f32 "
        "{%0,%1,%2,%3}, {%4,%5,%6,%7}, {%8,%9}, {%0,%1,%2,%3};"
        : "+f"(d[0]), "+f"(d[1]), "+f"(d[2]), "+f"(d[3])
        : "r"(a[0]), "r"(a[1]), "r"(a[2]), "r"(a[3]), "r"(b0), "r"(b1));
}

#define CP16(dst, src) \
    asm volatile("cp.async.cg.shared.global [%0], [%1], 16;" \
                 :: "r"(dst), "l"(src) : "memory")
#define CPCOMMIT() asm volatile("cp.async.commit_group;" ::: "memory")
#define CPWAIT(n)  asm volatile("cp.async.wait_group " #n ";" ::: "memory")

// ---------------- embedding gather (fp32 emb -> fp16 x) ----------------------
__global__ void embed16_k(const int* __restrict__ src, const float* __restrict__ emb) {
    int row = blockIdx.x;           // s*B + b
    int s = row >> 6;
    int b = row & 63;
    int v = src[b * Sq + s];
    float4 f = reinterpret_cast<const float4*>(emb + (size_t)v * Eq)[threadIdx.x];
    uint2 u;
    u.x = packh2(f.x, f.y);
    u.y = packh2(f.z, f.w);
    *reinterpret_cast<uint2*>(g_x16 + (size_t)row * Eq + threadIdx.x * 4) = u;
}

// ---------------- Whh fp32 -> fp16 (per layer, both directions) --------------
__global__ void whconv16_k(const float* __restrict__ Wf, const float* __restrict__ Wb) {
    size_t i = (size_t)blockIdx.x * blockDim.x + threadIdx.x;   // float4 index
    const size_t NF = (size_t)Gq * Hq / 4;
    float4 v = (i < NF) ? reinterpret_cast<const float4*>(Wf)[i]
                        : reinterpret_cast<const float4*>(Wb)[i - NF];
    uint2 u;
    u.x = packh2(v.x, v.y);
    u.y = packh2(v.z, v.w);
    reinterpret_cast<uint2*>(g_wh16)[i] = u;
}

// ---------------- fp16 mma.sync pre-gates GEMM -------------------------------
#define PST 20   // half2 row stride in smem chunk (16 data + 4 pad)
__global__ __launch_bounds__(256) void pregemm16(
    int insel, const float* __restrict__ W0, const float* __restrict__ bias,
    int dirout, int rev)
{
    __shared__ uint32_t As2[128 * PST];
    __shared__ uint32_t Ws2[128 * PST];
    __shared__ float s_bias[128];

    const __half* in16 = (insel == 0) ? g_x16 : ((insel == 1) ? g_h16[0] : g_h16[1]);
    float* gates = dirout ? g_gb : g_gf;

    const int n0 = blockIdx.x * 128;
    const int m0 = blockIdx.y * 128;
    const int tid = threadIdx.x;
    const int wid = tid >> 5;
    const int lane = tid & 31;
    const int warp_m = wid & 3;
    const int warp_n = wid >> 2;
    const int g = lane >> 2;
    const int c = lane & 3;

    if (tid < 128) s_bias[tid] = bias[n0 + tid];

    const int tr = tid >> 1;
    const int tc = tid & 1;
    const int m_in = m0 + tr;
    const int t_in = m_in >> 6, b_in = m_in & 63;
    const int tin = rev ? (Sq - 1 - t_in) : t_in;
    const __half* aptr = in16 + ((size_t)tin * Bq + b_in) * Eq + tc * 16;
    const float*  wptr = W0 + (size_t)(n0 + tr) * Eq + tc * 16;

    float acc[2][8][4];
#pragma unroll
    for (int mt = 0; mt < 2; mt++)
#pragma unroll
        for (int nt = 0; nt < 8; nt++)
#pragma unroll
            for (int r = 0; r < 4; r++) acc[mt][nt][r] = 0.0f;

    uint4 rau[2];
    float4 rwf[4];
    rau[0] = *reinterpret_cast<const uint4*>(aptr);
    rau[1] = *reinterpret_cast<const uint4*>(aptr + 8);
#pragma unroll
    for (int j = 0; j < 4; j++) rwf[j] = *reinterpret_cast<const float4*>(wptr + j * 4);

    for (int kc = 0; kc < Eq / 32; kc++) {
        __syncthreads();
        *reinterpret_cast<uint4*>(&As2[tr * PST + tc * 8])     = rau[0];
        *reinterpret_cast<uint4*>(&As2[tr * PST + tc * 8 + 4]) = rau[1];
        {
            uint4 w0, w1;
            w0.x = packh2(rwf[0].x, rwf[0].y); w0.y = packh2(rwf[0].z, rwf[0].w);
            w0.z = packh2(rwf[1].x, rwf[1].y); w0.w = packh2(rwf[1].z, rwf[1].w);
            w1.x = packh2(rwf[2].x, rwf[2].y); w1.y = packh2(rwf[2].z, rwf[2].w);
            w1.z = packh2(rwf[3].x, rwf[3].y); w1.w = packh2(rwf[3].z, rwf[3].w);
            *reinterpret_cast<uint4*>(&Ws2[tr * PST + tc * 8])     = w0;
            *reinterpret_cast<uint4*>(&Ws2[tr * PST + tc * 8 + 4]) = w1;
        }
        if (kc + 1 < Eq / 32) {
            int koff = (kc + 1) * 32;
            rau[0] = *reinterpret_cast<const uint4*>(aptr + koff);
            rau[1] = *reinterpret_cast<const uint4*>(aptr + koff + 8);
#pragma unroll
            for (int j = 0; j < 4; j++)
                rwf[j] = *reinterpret_cast<const float4*>(wptr + koff + j * 4);
        }
        __syncthreads();

#pragma unroll
        for (int ks = 0; ks < 2; ks++) {
            const int kb = ks * 8;
            uint32_t a[2][4];
#pragma unroll
            for (int mt = 0; mt < 2; mt++) {
                int row = warp_m * 32 + mt * 16;
                a[mt][0] = As2[(row + g) * PST + kb + c];
                a[mt][1] = As2[(row + 8 + g) * PST + kb + c];
                a[mt][2] = As2[(row + g) * PST + kb + c + 4];
                a[mt][3] = As2[(row + 8 + g) * PST + kb + c + 4];
            }
#pragma unroll
            for (int nt = 0; nt < 8; nt++) {
                int nb = warp_n * 64 + nt * 8;
                uint32_t b0 = Ws2[(nb + g) * PST + kb + c];
                uint32_t b1 = Ws2[(nb + g) * PST + kb + c + 4];
                mma_f16(acc[0][nt], a[0], b0, b1);
                mma_f16(acc[1][nt], a[1], b0, b1);
            }
        }
    }

#pragma unroll
    for (int mt = 0; mt < 2; mt++) {
        int r0 = m0 + warp_m * 32 + mt * 16 + g;
#pragma unroll
        for (int nt = 0; nt < 8; nt++) {
            int col = warp_n * 64 + nt * 8 + c * 2;
            float2 v0, v1;
            v0.x = acc[mt][nt][0] + s_bias[col];
            v0.y = acc[mt][nt][1] + s_bias[col + 1];
            v1.x = acc[mt][nt][2] + s_bias[col];
            v1.y = acc[mt][nt][3] + s_bias[col + 1];
            *reinterpret_cast<float2*>(&gates[(size_t)r0 * Gq + n0 + col]) = v0;
            *reinterpret_cast<float2*>(&gates[(size_t)(r0 + 8) * Gq + n0 + col]) = v1;
        }
    }
}

// ---------------- persistent fp16 recurrence, Whh RESIDENT in SMEM -----------
// 128 CTAs (cta = d*64 + q), 256 threads / 8 warps: warp_m(2) x warp_n(2) x kg(2).
// CTA's Whh slice (64 gate rows x 1024 halves = 128KB) loaded into smem once;
// per step only h(t-1) streams in 8 double-buffered 16KB chunks.
#define WST 516                        // half2 stride of resident Whh row (512+4)
#define HST 68                         // half2 stride of h chunk row (64+4)
#define HBUF5 (64 * HST)               // half2 per h chunk tile
#define WH5_OFF  0                                  // bytes
#define HB5_OFF  (64 * WST * 4)                     // 132096
#define SG5_OFF  (HB5_OFF + 2 * HBUF5 * 4)          // +34816
#define PRE5_OFF (SG5_OFF + 2 * 64 * 65 * 4)        // +33280
#define CS5_OFF  (PRE5_OFF + 64 * 64 * 4)           // +16384
#define HS5_OFF  (CS5_OFF + 16 * 65 * 4)            // +4160
#define SMEM5_BYTES (HS5_OFF + 64 * 16 * 2)         // +2048 = 222784

__global__ __launch_bounds__(256) void steps5_k(int l)
{
    extern __shared__ char smc[];
    uint32_t* wh_s  = reinterpret_cast<uint32_t*>(smc + WH5_OFF);   // 64 x WST half2
    float*    sg    = reinterpret_cast<float*>(smc + SG5_OFF);      // 2 x (64x65)
    float*    pre_s = reinterpret_cast<float*>(smc + PRE5_OFF);     // 64x64
    float*    c_s   = reinterpret_cast<float*>(smc + CS5_OFF);      // 16x65
    __half*   h16_s = reinterpret_cast<__half*>(smc + HS5_OFF);     // 64x16

    const int cta = blockIdx.x;
    const int d = cta >> 6;
    const int q = cta & 63;
    const float*  pre = d ? g_gb : g_gf;
    const __half* whb = g_wh16 + (size_t)d * Gq * Hq;
    __half* hseq = g_h16[l * 2 + d];

    const int tid = threadIdx.x;
    const int wid = tid >> 5;
    const int lane = tid & 31;
    const int warp_m = wid & 1;
    const int warp_n = (wid >> 1) & 1;
    const int kg = wid >> 2;
    const int g_ = lane >> 2;
    const int c_ = lane & 3;

    const uint32_t sbase = smem_u32(smc);

    // ---- one-time resident Whh load: 64 rows x 128 uint4 -------------------
    {
        // thread covers u4 index = (tid&31) + 32*j within row (tid>>5)+8*jr
        for (int it = 0; it < 32; it++) {
            int f = tid + it * 256;            // 0..8191
            int row = f >> 7;                  // 0..63
            int u4 = f & 127;                  // uint4 within row
            int gr = (row >> 4) * 1024 + q * 16 + (row & 15);
            const __half* src = whb + (size_t)gr * Hq + u4 * 8;
            uint32_t dst = sbase + (uint32_t)(WH5_OFF + row * (WST * 4) + u4 * 16);
            CP16(dst, src);
        }
        CPCOMMIT();
    }

    // h chunk cp.async mapping: f = tid + j*256 -> row = f>>4 (0..63), c16 = f&15
    const int hr = -1; (void)hr;

    const unsigned e = g_epoch;

    for (int i = tid; i < 16 * 65; i += 256) c_s[i] = 0.0f;
    CPWAIT(0);
    __syncthreads();   // Whh resident + c_s ready

    const int u = tid & 15;          // local unit
    const int bg = tid >> 4;         // batch group (4 batches)

    for (int t = 0; t < Sq; t++) {
        // stage pre-gates (fp32): 1024 x 16B over 256 threads
#pragma unroll
        for (int j = 0; j < 4; j++) {
            int idx = tid + j * 256;
            int b = idx >> 4, rem = idx & 15;
            int gg = rem >> 2, qt = rem & 3;
            const float* src = pre + ((size_t)t * Bq + b) * Gq + gg * 1024 + q * 16 + qt * 4;
            uint32_t dst = sbase + (uint32_t)(PRE5_OFF + (b * 64 + gg * 16 + qt * 4) * 4);
            CP16(dst, src);
        }
        CPCOMMIT();

        float acc[2][4][4];
#pragma unroll
        for (int mt = 0; mt < 2; mt++)
#pragma unroll
            for (int nt = 0; nt < 4; nt++)
#pragma unroll
                for (int r = 0; r < 4; r++) acc[mt][nt][r] = 0.0f;

        if (t > 0) {
            const __half* hprev = hseq + (size_t)(t - 1) * Bq * Hq;
            auto issue = [&](int ic) {
                int k0 = ic * 128;                          // halves
                uint32_t hb = sbase + (uint32_t)(HB5_OFF + (ic & 1) * HBUF5 * 4);
#pragma unroll
                for (int j = 0; j < 4; j++) {
                    int f = tid + j * 256;
                    int row = f >> 4;                       // 0..63
                    int c16 = f & 15;                       // uint4 in row
                    CP16(hb + (uint32_t)(row * (HST * 4) + c16 * 16),
                         hprev + (size_t)row * Hq + k0 + c16 * 8);
                }
            };
            issue(0); CPCOMMIT();
            issue(1); CPCOMMIT();
            for (int ic = 0; ic < 8; ic++) {
                if (ic < 7) { CPWAIT(1); } else { CPWAIT(0); }
                __syncthreads();
                const uint32_t* Asm = reinterpret_cast<const uint32_t*>(
                    smc + HB5_OFF + (size_t)(ic & 1) * HBUF5 * 4);
                const uint32_t* Bsm = wh_s + ic * 64;       // half2 col offset
#pragma unroll
                for (int ks = 0; ks < 4; ks++) {
                    const int kb = kg * 32 + ks * 8;        // half2 within chunk
                    uint32_t a[2][4];
#pragma unroll
                    for (int mt = 0; mt < 2; mt++) {
                        int rr = warp_m * 32 + mt * 16;
                        a[mt][0] = Asm[(rr + g_) * HST + kb + c_];
                        a[mt][1] = Asm[(rr + 8 + g_) * HST + kb + c_];
                        a[mt][2] = Asm[(rr + g_) * HST + kb + c_ + 4];
                        a[mt][3] = Asm[(rr + 8 + g_) * HST + kb + c_ + 4];
                    }
#pragma unroll
                    for (int nt = 0; nt < 4; nt++) {
                        int nb = warp_n * 32 + nt * 8;
                        uint32_t b0 = Bsm[(nb + g_) * WST + kb + c_];
                        uint32_t b1 = Bsm[(nb + g_) * WST + kb + c_ + 4];
                        mma_f16(acc[0][nt], a[0], b0, b1);
                        mma_f16(acc[1][nt], a[1], b0, b1);
                    }
                }
                __syncthreads();
                if (ic + 2 < 8) { issue(ic + 2); CPCOMMIT(); }
            }
        } else {
            CPWAIT(0);
            __syncthreads();
        }

        // acc -> sg[kg][n_local][batch]
        float* sgk = sg + kg * (64 * 65);
#pragma unroll
        for (int mt = 0; mt < 2; mt++) {
            int ml = warp_m * 32 + mt * 16 + g_;
#pragma unroll
            for (int nt = 0; nt < 4; nt++) {
                int nl = warp_n * 32 + nt * 8 + c_ * 2;
                sgk[nl * 65 + ml]           = acc[mt][nt][0];
                sgk[(nl + 1) * 65 + ml]     = acc[mt][nt][1];
                sgk[nl * 65 + ml + 8]       = acc[mt][nt][2];
                sgk[(nl + 1) * 65 + ml + 8] = acc[mt][nt][3];
            }
        }
        __syncthreads();

        // activations: thread = (unit u, batch group bg), 4 batches
#pragma unroll
        for (int j = 0; j < 4; j++) {
            int b = bg * 4 + j;
            float gi = sg[u * 65 + b]        + sg[64*65 + u * 65 + b]        + pre_s[b * 64 + u];
            float gf = sg[(16 + u) * 65 + b] + sg[64*65 + (16 + u) * 65 + b] + pre_s[b * 64 + 16 + u];
            float gg = sg[(32 + u) * 65 + b] + sg[64*65 + (32 + u) * 65 + b] + pre_s[b * 64 + 32 + u];
            float go = sg[(48 + u) * 65 + b] + sg[64*65 + (48 + u) * 65 + b] + pre_s[b * 64 + 48 + u];
            float cold = c_s[u * 65 + b];
            float cnew = sigf(gf) * cold + sigf(gi) * tanhfast(gg);
            c_s[u * 65 + b] = cnew;
            h16_s[b * 16 + u] = __float2half_rn(sigf(go) * tanhfast(cnew));
        }
        __syncthreads();

        // coalesced STG of h16(t): 128 threads x 16B
        if (tid < 128) {
            int b = tid >> 1, hp = tid & 1;
            uint4 v = *reinterpret_cast<const uint4*>(h16_s + b * 16 + hp * 8);
            *reinterpret_cast<uint4*>(
                &hseq[((size_t)t * Bq + b) * Hq + q * 16 + hp * 8]) = v;
        }

        // per-direction grid barrier (release h(t))
        __syncthreads();
        __threadfence();
        if (tid == 0) g_flags[cta] = e + t + 1;
        if (tid < 64) {
            unsigned tgt = e + t + 1;
            while (g_flags[d * 64 + tid] < tgt) __nanosleep(64);
        }
        __syncthreads();
    }

    if (cta == 0 && tid == 0) g_epoch = e + Sq;
}

// ---------------- output GEMM: out = concat(f, r_rev) @ Wout^T + bout --------
__global__ __launch_bounds__(256) void outgemm16(
    const float* __restrict__ Wout, const float* __restrict__ bout,
    float* __restrict__ out)
{
    __shared__ float As[16][64];
    __shared__ float Ws[16][64];
    int s = blockIdx.x;
    int tid = threadIdx.x;
    int lm = tid >> 4, lk = tid & 15;
    int ty = lm, tx = lk;

    const __half* fbase = g_h16[2] + (size_t)s * Bq * Hq;
    const __half* rbase = g_h16[3] + (size_t)(Sq - 1 - s) * Bq * Hq;

    float acc[4][4];
#pragma unroll
    for (int i = 0; i < 4; i++)
#pragma unroll
        for (int j = 0; j < 4; j++) acc[i][j] = 0.0f;

    for (int k0 = 0; k0 < KOUT; k0 += 16) {
        const __half* A = (k0 < Hq) ? fbase : rbase;
        int ka = (k0 < Hq) ? k0 : (k0 - Hq);
#pragma unroll
        for (int i = 0; i < 4; i++) {
            As[lk][lm + i * 16] = __half2float(A[(size_t)(lm + i * 16) * Hq + ka + lk]);
            int n = lm + i * 16;
            Ws[lk][lm + i * 16] = (n < Oq) ? Wout[(size_t)n * KOUT + k0 + lk] : 0.0f;
        }
        __syncthreads();
#pragma unroll
        for (int kk = 0; kk < 16; kk++) {
            float4 av = *reinterpret_cast<const float4*>(&As[kk][ty * 4]);
            float4 wv = *reinterpret_cast<const float4*>(&Ws[kk][tx * 4]);
            float a[4] = {av.x, av.y, av.z, av.w};
            float w[4] = {wv.x, wv.y, wv.z, wv.w};
#pragma unroll
            for (int i = 0; i < 4; i++)
#pragma unroll
                for (int j = 0; j < 4; j++) acc[i][j] += a[i] * w[j];
        }
        __syncthreads();
    }

#pragma unroll
    for (int i = 0; i < 4; i++) {
        int b = ty * 4 + i;
#pragma unroll
        for (int j = 0; j < 4; j++) {
            int n = tx * 4 + j;
            if (n < Oq)
                out[((size_t)b * Sq + s) * Oq + n] = acc[i][j] + bout[n];
        }
    }
}

// ---------------- launcher ----------------------------------------------------
extern "C" void kernel_launch(void* const* d_in, const int* in_sizes, int n_in,
                              void* d_out, int out_size)
{
    const int*   src   = (const int*)  d_in[0];
    const float* emb   = (const float*)d_in[1];
    const float* Wih_f = (const float*)d_in[2];
    const float* Whh_f = (const float*)d_in[3];
    const float* b_f   = (const float*)d_in[4];
    const float* Wih_b = (const float*)d_in[5];
    const float* Whh_b = (const float*)d_in[6];
    const float* b_b   = (const float*)d_in[7];
    const float* Wout  = (const float*)d_in[8];
    const float* bout  = (const float*)d_in[9];
    float* out = (float*)d_out;

    cudaFuncSetAttribute(steps5_k,
                         cudaFuncAttributeMaxDynamicSharedMemorySize, SMEM5_BYTES);

    embed16_k<<<Sq * Bq, 256>>>(src, emb);

    for (int l = 0; l < 2; l++) {
        pregemm16<<<dim3(32, 256), 256>>>(
            (l == 0) ? 0 : 1, Wih_f + (size_t)l * Gq * Eq, b_f + l * Gq, 0, 0);
        pregemm16<<<dim3(32, 256), 256>>>(
            (l == 0) ? 0 : 2, Wih_b + (size_t)l * Gq * Eq, b_b + l * Gq, 1,
            (l == 0) ? 1 : 0);

        whconv16_k<<<(2 * Gq * (Hq / 4)) / 256, 256>>>(
            Whh_f + (size_t)l * Gq * Hq, Whh_b + (size_t)l * Gq * Hq);

        steps5_k<<<128, 256, SMEM5_BYTES>>>(l);
    }

    outgemm16<<<Sq, 256>>>(Wout, bout, out);
}